// round 15
// baseline (speedup 1.0000x reference)
#include <cuda_runtime.h>
#include <cuda_bf16.h>
#include <math.h>
#include <stdint.h>

#define Bb   4
#define Nn   1024
#define Dd   512
#define Hh   8
#define DHh  64
#define HIDn 32

// ---------------------------------------------------------------------------
// Static scratch (allocation-free per harness rules)
// ---------------------------------------------------------------------------
__device__ float g_bias[(size_t)Bb*Hh*Nn*Nn];     // [B,H,N,N] additive bias

// bf16 hi/lo operands
__device__ __nv_bfloat16 g_xh[4096*512],  g_xl[4096*512];    // x          [M,K]
__device__ __nv_bfloat16 g_wth[1536*512], g_wtl[1536*512];   // qkv_w^T    [N,K]
__device__ __nv_bfloat16 g_ath[4096*512], g_atl[4096*512];   // att        [M,K]
__device__ __nv_bfloat16 g_owth[512*512], g_owtl[512*512];   // out_w^T    [N,K]
__device__ __nv_bfloat16 g_qh[Bb*Hh*Nn*DHh], g_ql[Bb*Hh*Nn*DHh];  // q (x0.125)
__device__ __nv_bfloat16 g_kh[Bb*Hh*Nn*DHh], g_kl[Bb*Hh*Nn*DHh];
__device__ __nv_bfloat16 g_vh[Bb*Hh*Nn*DHh], g_vl[Bb*Hh*Nn*DHh];

// ---------------------------------------------------------------------------
// Packed fp32x2 FMA (k_bias only — operands pack cleanly there)
// ---------------------------------------------------------------------------
__device__ __forceinline__ float2 ffma2(float2 a, float2 b, float2 c) {
    float2 d;
    asm("fma.rn.f32x2 %0, %1, %2, %3;"
        : "=l"(*(unsigned long long*)&d)
        : "l"(*(unsigned long long*)&a),
          "l"(*(unsigned long long*)&b),
          "l"(*(unsigned long long*)&c));
    return d;
}

// Branch-free exact-GELU (A&S 7.1.26 5-term erf, |err| <= 1.5e-7)
__device__ __forceinline__ float gelu_exact(float x) {
    float z = 0.70710678118654752f * fabsf(x);
    float d = fmaf(0.3275911f, z, 1.0f);
    float t;
    asm("rcp.approx.f32 %0, %1;" : "=f"(t) : "f"(d));
    float p = fmaf(1.061405429f, t, -1.453152027f);
    p = fmaf(p, t, 1.421413741f);
    p = fmaf(p, t, -0.284496736f);
    p = fmaf(p, t, 0.254829592f);
    p *= t;
    float e = __expf(-z * z);
    float erfv = fmaf(-p, e, 1.0f);
    erfv = copysignf(erfv, x);
    float hx = 0.5f * x;
    return fmaf(hx, erfv, hx);
}

// ---------------------------------------------------------------------------
// mma.sync / ldmatrix / cp.async helpers (baseline PTX, OK on plain sm_103)
// ---------------------------------------------------------------------------
__device__ __forceinline__ uint32_t smem_u32(const void* p) {
    uint32_t a;
    asm("{ .reg .u64 t; cvta.to.shared.u64 t, %1; cvt.u32.u64 %0, t; }" : "=r"(a) : "l"(p));
    return a;
}
__device__ __forceinline__ void ldsm4(uint32_t r[4], uint32_t addr) {
    asm volatile("ldmatrix.sync.aligned.m8n8.x4.shared.b16 {%0,%1,%2,%3}, [%4];"
        : "=r"(r[0]), "=r"(r[1]), "=r"(r[2]), "=r"(r[3]) : "r"(addr));
}
__device__ __forceinline__ void ldsm4t(uint32_t r[4], uint32_t addr) {
    asm volatile("ldmatrix.sync.aligned.m8n8.x4.trans.shared.b16 {%0,%1,%2,%3}, [%4];"
        : "=r"(r[0]), "=r"(r[1]), "=r"(r[2]), "=r"(r[3]) : "r"(addr));
}
__device__ __forceinline__ void mma16816(float c[4], const uint32_t a[4], const uint32_t b[2]) {
    asm volatile("mma.sync.aligned.m16n8k16.row.col.f32.bf16.bf16.f32 "
        "{%0,%1,%2,%3}, {%4,%5,%6,%7}, {%8,%9}, {%0,%1,%2,%3};"
        : "+f"(c[0]), "+f"(c[1]), "+f"(c[2]), "+f"(c[3])
        : "r"(a[0]), "r"(a[1]), "r"(a[2]), "r"(a[3]), "r"(b[0]), "r"(b[1]));
}
__device__ __forceinline__ void cp16(uint32_t dst, const void* src) {
    asm volatile("cp.async.ca.shared.global [%0], [%1], 16;" :: "r"(dst), "l"(src));
}
#define CP_COMMIT() asm volatile("cp.async.commit_group;" ::: "memory")
#define CP_WAIT(n)  asm volatile("cp.async.wait_group %0;" :: "n"(n) : "memory")

#define TP 40   // GEMM smem tile pitch (bf16)

// ---------------------------------------------------------------------------
// hi/lo bf16 split kernels (input x + weight transposes)
// ---------------------------------------------------------------------------
__global__ __launch_bounds__(256) void k_split_x(const float4* __restrict__ src) {
    size_t i = (size_t)blockIdx.x * 256 + threadIdx.x;
    float4 v = src[i];
    float a[4] = {v.x, v.y, v.z, v.w};
    __nv_bfloat16 h[4], l[4];
    #pragma unroll
    for (int j = 0; j < 4; j++) {
        h[j] = __float2bfloat16_rn(a[j]);
        l[j] = __float2bfloat16_rn(a[j] - __bfloat162float(h[j]));
    }
    ((__nv_bfloat162*)g_xh)[2*i]   = __halves2bfloat162(h[0], h[1]);
    ((__nv_bfloat162*)g_xh)[2*i+1] = __halves2bfloat162(h[2], h[3]);
    ((__nv_bfloat162*)g_xl)[2*i]   = __halves2bfloat162(l[0], l[1]);
    ((__nv_bfloat162*)g_xl)[2*i+1] = __halves2bfloat162(l[2], l[3]);
}

__global__ void k_splitT(const float* __restrict__ src, int K, int N, int which) {
    __shared__ float ts[32][33];
    int kk = blockIdx.y * 32 + threadIdx.y;
    int nn = blockIdx.x * 32 + threadIdx.x;
    ts[threadIdx.y][threadIdx.x] = src[(size_t)kk * N + nn];
    __syncthreads();
    int on = blockIdx.x * 32 + threadIdx.y;
    int ok = blockIdx.y * 32 + threadIdx.x;
    float v = ts[threadIdx.x][threadIdx.y];
    __nv_bfloat16 h = __float2bfloat16_rn(v);
    __nv_bfloat16 l = __float2bfloat16_rn(v - __bfloat162float(h));
    __nv_bfloat16* hd = which ? g_owth : g_wth;
    __nv_bfloat16* ld = which ? g_owtl : g_wtl;
    hd[(size_t)on * K + ok] = h;
    ld[(size_t)on * K + ok] = l;
}

// ---------------------------------------------------------------------------
// HMMA bf16x3 GEMM mainloop — cp.async double-buffered (unchanged)
// ---------------------------------------------------------------------------
#define TILE_B   (128 * TP * 2)
#define BUF_B    (4 * TILE_B)
#define GEMM_SMEM (2 * BUF_B)

__device__ __forceinline__ void cp_tile(uint32_t dst, const __nv_bfloat16* __restrict__ src,
                                        int row0, int k0, int tid) {
    #pragma unroll
    for (int i = 0; i < 2; i++) {
        int idx = tid + (i << 8);
        int rr = idx >> 2, sg = idx & 3;
        cp16(dst + (uint32_t)((rr * TP) * 2 + sg * 16),
             (const char*)src + ((size_t)(row0 + rr) * 512 + k0) * 2 + sg * 16);
    }
}

__device__ __forceinline__ void issue_chunk(uint32_t sb, int buf,
    const __nv_bfloat16* Ah, const __nv_bfloat16* Al,
    const __nv_bfloat16* Bh, const __nv_bfloat16* Bl,
    int m0, int n0, int k0, int tid)
{
    uint32_t b = sb + buf * BUF_B;
    cp_tile(b + 0 * TILE_B, Ah, m0, k0, tid);
    cp_tile(b + 1 * TILE_B, Al, m0, k0, tid);
    cp_tile(b + 2 * TILE_B, Bh, n0, k0, tid);
    cp_tile(b + 3 * TILE_B, Bl, n0, k0, tid);
    CP_COMMIT();
}

__device__ __forceinline__ void mma_all(float acc[4][4][4],
                                        const uint32_t a[4][4],
                                        const uint32_t b[4][2]) {
    #pragma unroll
    for (int mt = 0; mt < 4; mt++)
        #pragma unroll
        for (int nt = 0; nt < 4; nt++)
            mma16816(acc[mt][nt], a[mt], b[nt]);
}

__device__ __forceinline__ void load_afrag(uint32_t a[4][4], uint32_t base_u32,
                                           int wyBase, int kb, int lane) {
    int r  = wyBase + (lane & 15);
    int kc = (kb << 4) + ((lane >> 4) << 3);
    uint32_t addr = base_u32 + (uint32_t)(r * TP + kc) * 2;
    #pragma unroll
    for (int mt = 0; mt < 4; mt++)
        ldsm4(a[mt], addr + mt * (16 * TP * 2));
}

__device__ __forceinline__ void load_bfrag(uint32_t b[4][2], uint32_t base_u32,
                                           int wxBase, int kb, int lane) {
    int n  = wxBase + (((lane >> 4) & 1) << 3) + (lane & 7);
    int kc = (kb << 4) + (((lane >> 3) & 1) << 3);
    uint32_t addr = base_u32 + (uint32_t)(n * TP + kc) * 2;
    #pragma unroll
    for (int np = 0; np < 2; np++) {
        uint32_t t4[4];
        ldsm4(t4, addr + np * (16 * TP * 2));
        b[np * 2 + 0][0] = t4[0]; b[np * 2 + 0][1] = t4[1];
        b[np * 2 + 1][0] = t4[2]; b[np * 2 + 1][1] = t4[3];
    }
}

__device__ __forceinline__ void hmma_mainloop(
    float acc[4][4][4], char* smem,
    const __nv_bfloat16* Ah, const __nv_bfloat16* Al,
    const __nv_bfloat16* Bh, const __nv_bfloat16* Bl,
    int m0, int n0, int tid)
{
    int lane = tid & 31, wid = tid >> 5;
    int wyBase = (wid >> 2) * 64, wxBase = (wid & 3) * 32;
    uint32_t sb = smem_u32(smem);

    issue_chunk(sb, 0, Ah, Al, Bh, Bl, m0, n0, 0, tid);
    #pragma unroll 1
    for (int c = 0; c < 16; c++) {
        if (c < 15) {
            issue_chunk(sb, (c + 1) & 1, Ah, Al, Bh, Bl, m0, n0, (c + 1) * 32, tid);
            CP_WAIT(1);
        } else {
            CP_WAIT(0);
        }
        __syncthreads();
        uint32_t base = sb + (c & 1) * BUF_B;
        uint32_t uAh = base, uAl = base + TILE_B;
        uint32_t uBh = base + 2 * TILE_B, uBl = base + 3 * TILE_B;
        #pragma unroll
        for (int kb = 0; kb < 2; kb++) {
            uint32_t a[4][4], b[4][2];
            load_afrag(a, uAh, wyBase, kb, lane);
            load_bfrag(b, uBl, wxBase, kb, lane);
            mma_all(acc, a, b);
            load_bfrag(b, uBh, wxBase, kb, lane);
            mma_all(acc, a, b);
            load_afrag(a, uAl, wyBase, kb, lane);
            mma_all(acc, a, b);
        }
        __syncthreads();
    }
}

// ---------------------------------------------------------------------------
// K1: QKV projection on HMMA; epilogue writes q/k/v as bf16 hi/lo (q x0.125).
// ---------------------------------------------------------------------------
__global__ __launch_bounds__(256, 2) void k_qkv_mma() {
    extern __shared__ char smg[];
    int tid = threadIdx.x;
    int n0 = blockIdx.x << 7, m0 = blockIdx.y << 7;

    float acc[4][4][4];
    #pragma unroll
    for (int mt = 0; mt < 4; mt++)
        #pragma unroll
        for (int nt = 0; nt < 4; nt++)
            acc[mt][nt][0] = acc[mt][nt][1] = acc[mt][nt][2] = acc[mt][nt][3] = 0.0f;

    hmma_mainloop(acc, smg, g_xh, g_xl, g_wth, g_wtl, m0, n0, tid);

    int lane = tid & 31, wid = tid >> 5;
    int wyBase = (wid >> 2) * 64, wxBase = (wid & 3) * 32;
    int g = lane >> 2, tig = lane & 3;

    int sec = n0 >> 9;
    float s = (sec == 0) ? 0.125f : 1.0f;
    __nv_bfloat16* dh = (sec == 0) ? g_qh : (sec == 1) ? g_kh : g_vh;
    __nv_bfloat16* dl = (sec == 0) ? g_ql : (sec == 1) ? g_kl : g_vl;

    #pragma unroll
    for (int mt = 0; mt < 4; mt++) {
        #pragma unroll
        for (int nt = 0; nt < 4; nt++) {
            int col = n0 + wxBase + (nt << 3) + (tig << 1);
            int h = (col & 511) >> 6, e = col & 63;
            #pragma unroll
            for (int half = 0; half < 2; half++) {
                int row = m0 + wyBase + (mt << 4) + g + (half << 3);
                int b = row >> 10, n = row & 1023;
                float v0 = acc[mt][nt][half * 2]     * s;
                float v1 = acc[mt][nt][half * 2 + 1] * s;
                __nv_bfloat162 hp = __float22bfloat162_rn(make_float2(v0, v1));
                __nv_bfloat162 lp = __float22bfloat162_rn(make_float2(
                    v0 - __bfloat162float(hp.x), v1 - __bfloat162float(hp.y)));
                size_t off = ((size_t)((b << 3) + h) * Nn + n) * DHh + e;
                *(__nv_bfloat162*)(dh + off) = hp;
                *(__nv_bfloat162*)(dl + off) = lp;
            }
        }
    }
}

// ---------------------------------------------------------------------------
// K4: output projection on HMMA. out = att @ out_w + out_b
// ---------------------------------------------------------------------------
__global__ __launch_bounds__(256, 2) void k_out_mma(const float* __restrict__ bias,
                                                    float* __restrict__ out) {
    extern __shared__ char smg[];
    int tid = threadIdx.x;
    int n0 = blockIdx.x << 7, m0 = blockIdx.y << 7;

    float acc[4][4][4];
    #pragma unroll
    for (int mt = 0; mt < 4; mt++)
        #pragma unroll
        for (int nt = 0; nt < 4; nt++)
            acc[mt][nt][0] = acc[mt][nt][1] = acc[mt][nt][2] = acc[mt][nt][3] = 0.0f;

    hmma_mainloop(acc, smg, g_ath, g_atl, g_owth, g_owtl, m0, n0, tid);

    int lane = tid & 31, wid = tid >> 5;
    int wyBase = (wid >> 2) * 64, wxBase = (wid & 3) * 32;
    int g = lane >> 2, tig = lane & 3;

    #pragma unroll
    for (int mt = 0; mt < 4; mt++) {
        #pragma unroll
        for (int nt = 0; nt < 4; nt++) {
            int col = n0 + wxBase + (nt << 3) + (tig << 1);
            float2 bv = *(const float2*)(bias + col);
            #pragma unroll
            for (int half = 0; half < 2; half++) {
                int row = m0 + wyBase + (mt << 4) + g + (half << 3);
                *(float2*)(out + (size_t)row * Dd + col) =
                    make_float2(acc[mt][nt][half * 2] + bv.x,
                                acc[mt][nt][half * 2 + 1] + bv.y);
            }
        }
    }
}

// ---------------------------------------------------------------------------
// K2: bias MLP v4 — k_proj fused in (U recomputed in-smem from coords+w1).
// FIX vs R14: ci AND cj are both loaded by threads tid<96 (full 96 entries
// each) — the R14 predicate left cj[64:96) uninitialized.
// ---------------------------------------------------------------------------
__global__ __launch_bounds__(256) void k_bias(const float* __restrict__ coords,
                                              const float* __restrict__ w1,
                                              const float* __restrict__ b1,
                                              const float* __restrict__ w2,
                                              const float* __restrict__ b2) {
    __shared__ float  sUi[32 * 33];
    __shared__ float  sUj[32 * 33];
    __shared__ float  sw1[96];
    __shared__ float  sb1v[32];
    __shared__ float  ci[32][3];
    __shared__ float  cj[32][3];
    __shared__ float2 sw2[HIDn * 4];
    __shared__ float2 sb2v[4];

    int b  = blockIdx.z;
    int i0 = blockIdx.y << 5;
    int j0 = blockIdx.x << 5;
    int tid = threadIdx.x;

    if (tid < 96) {
        sw1[tid] = w1[tid];
        int r = tid / 3, c = tid % 3;
        ci[r][c] = coords[((size_t)(b << 10) + i0 + r) * 3 + c];
        cj[r][c] = coords[((size_t)(b << 10) + j0 + r) * 3 + c];
    }
    if (tid < 32)  sb1v[tid] = b1[tid];
    if (tid >= 128) {
        int t = tid - 128;
        int m = t >> 2, hp = t & 3;
        sw2[m * 4 + hp] = *(const float2*)(w2 + m * Hh + (hp << 1));
    }
    if (tid >= 96 && tid < 100) sb2v[tid - 96] = *(const float2*)(b2 + ((tid - 96) << 1));
    __syncthreads();

    // compute U tiles in-smem (fused k_proj): 4 entries each of sUi/sUj per thread
    #pragma unroll
    for (int k = 0; k < 4; k++) {
        int idx = tid + (k << 8);
        int r = idx >> 5, m = idx & 31;
        float w0 = sw1[m], w1v = sw1[32 + m], w2v = sw1[64 + m];
        sUi[r * 33 + m] = fmaf(ci[r][0], w0, fmaf(ci[r][1], w1v,
                           fmaf(ci[r][2], w2v, sb1v[m])));
        sUj[r * 33 + m] = fmaf(cj[r][0], w0, fmaf(cj[r][1], w1v, cj[r][2] * w2v));
    }
    __syncthreads();

    int j  = tid & 31;
    int ib = tid >> 5;                       // i = ib + 8q
    const float* uj = sUj + j * 33;
    const float* ui = sUi + ib * 33;

    float2 acc[4][4];
    #pragma unroll
    for (int q = 0; q < 4; q++) {
        acc[q][0] = sb2v[0]; acc[q][1] = sb2v[1];
        acc[q][2] = sb2v[2]; acc[q][3] = sb2v[3];
    }

    #pragma unroll 8
    for (int m = 0; m < HIDn; m++) {
        float ujm = uj[m];
        float2 w0 = sw2[m * 4 + 0], w1v = sw2[m * 4 + 1];
        float2 w2v = sw2[m * 4 + 2], w3v = sw2[m * 4 + 3];
        #pragma unroll
        for (int q = 0; q < 4; q++) {
            float g = gelu_exact(ui[q * 264 + m] - ujm);   // 264 = 8*33
            float2 gg = make_float2(g, g);
            acc[q][0] = ffma2(gg, w0,  acc[q][0]);
            acc[q][1] = ffma2(gg, w1v, acc[q][1]);
            acc[q][2] = ffma2(gg, w2v, acc[q][2]);
            acc[q][3] = ffma2(gg, w3v, acc[q][3]);
        }
    }

    #pragma unroll
    for (int q = 0; q < 4; q++) {
        int i = ib + (q << 3);
        size_t base = ((size_t)((b * Hh) << 10) + i0 + i) * Nn + j0 + j;
        float av[8] = {acc[q][0].x, acc[q][0].y, acc[q][1].x, acc[q][1].y,
                       acc[q][2].x, acc[q][2].y, acc[q][3].x, acc[q][3].y};
        #pragma unroll
        for (int h = 0; h < Hh; h++)
            g_bias[base + (size_t)h * (Nn * Nn)] = av[h];
    }
}

// ---------------------------------------------------------------------------
// K3: HMMA flash attention — 128 threads / 64 i-rows per CTA (2 CTAs/SM),
// cp.async double-buffered K/V. smem: 2x36864 (KV) + 2x9216 (P) = 92160 B.
// ---------------------------------------------------------------------------
#define KVBUF   36864
#define AOFF_PH 73728
#define AOFF_PL 82944
#define AT_SMEM 92160

__device__ __forceinline__ void attn_issue_kv(uint32_t sb, int buf,
    const __nv_bfloat16* Kh, const __nv_bfloat16* Kl,
    const __nv_bfloat16* Vh, const __nv_bfloat16* Vl, int j0, int tid)
{
    // 128 threads: each covers 64B of one row (2 threads/row)
    int row = tid >> 1, off = (tid & 1) * 64;
    size_t go = (size_t)(j0 + row) * DHh;
    uint32_t d = sb + (uint32_t)(buf * KVBUF + row * 144 + off);
    #pragma unroll
    for (int q = 0; q < 4; q++) {
        int qo = q * 16;
        cp16(d + qo,         (const char*)(Kh + go) + off + qo);
        cp16(d + 9216 + qo,  (const char*)(Kl + go) + off + qo);
        cp16(d + 18432 + qo, (const char*)(Vh + go) + off + qo);
        cp16(d + 27648 + qo, (const char*)(Vl + go) + off + qo);
    }
    CP_COMMIT();
}

__global__ __launch_bounds__(128) void k_attn_mma(const unsigned char* __restrict__ mask) {
    extern __shared__ char smx[];
    uint32_t sb = smem_u32(smx);
    int tid = threadIdx.x, lane = tid & 31, w = tid >> 5;   // w in [0,4)
    int g = lane >> 2, tig = lane & 3;
    int bh = blockIdx.y, i0 = blockIdx.x << 6;              // 64-row i-tile
    int b = bh >> 3, h = bh & 7;

    const __nv_bfloat16* Qh = g_qh + (size_t)bh * Nn * DHh;
    const __nv_bfloat16* Ql = g_ql + (size_t)bh * Nn * DHh;
    const __nv_bfloat16* Kh = g_kh + (size_t)bh * Nn * DHh;
    const __nv_bfloat16* Kl = g_kl + (size_t)bh * Nn * DHh;
    const __nv_bfloat16* Vh = g_vh + (size_t)bh * Nn * DHh;
    const __nv_bfloat16* Vl = g_vl + (size_t)bh * Nn * DHh;
    const unsigned char* mrow = mask + ((size_t)b << 10);
    int r0 = i0 + w * 16 + g;
    const float* br0 = g_bias + (size_t)bh * Nn * Nn + (size_t)r0 * Nn;
    const float* br1 = br0 + 8 * Nn;

    // prefetch first K/V tile while staging Q
    attn_issue_kv(sb, 0, Kh, Kl, Vh, Vl, 0, tid);

    // stage Q fragments into registers (hi then lo, via P buffer)
    // 64 rows x 128B: 128 threads, each one 128B row
    uint32_t qfh[4][4], qfl[4][4];
    #pragma unroll
    for (int pass = 0; pass < 2; pass++) {
        const __nv_bfloat16* src = pass ? Ql : Qh;
        int row = tid;
        const uint4* s4 = (const uint4*)(src + (size_t)(i0 + row) * DHh);
        uint4* d4 = (uint4*)(smx + AOFF_PH + row * 144);
        #pragma unroll
        for (int q = 0; q < 8; q++) d4[q] = s4[q];
        __syncthreads();
        uint32_t base = sb + AOFF_PH + (uint32_t)((w * 16 + (lane & 15)) * 144 + ((lane >> 4) << 4));
        #pragma unroll
        for (int ks = 0; ks < 4; ks++)
            ldsm4(pass ? qfl[ks] : qfh[ks], base + ks * 32);
        __syncthreads();
    }

    float o[8][4];
    #pragma unroll
    for (int nt = 0; nt < 8; nt++)
        o[nt][0] = o[nt][1] = o[nt][2] = o[nt][3] = 0.0f;
    float m0 = -1e30f, m1 = -1e30f, l0 = 0.0f, l1 = 0.0f;

    #pragma unroll 1
    for (int jt = 0; jt < 16; jt++) {
        int j0 = jt << 6;
        CP_WAIT(0);
        __syncthreads();                       // KV ready; prior PV reads done
        if (jt < 15)
            attn_issue_kv(sb, (jt + 1) & 1, Kh, Kl, Vh, Vl, (jt + 1) << 6, tid);

        uint32_t kvb = sb + (uint32_t)((jt & 1) * KVBUF);

        // init S accumulators with bias (MMA accumulates on top)
        float s[8][4];
        #pragma unroll
        for (int nt = 0; nt < 8; nt++) {
            int col = j0 + (nt << 3) + (tig << 1);
            float2 b0 = *(const float2*)(br0 + col);
            float2 b1 = *(const float2*)(br1 + col);
            s[nt][0] = b0.x; s[nt][1] = b0.y;
            s[nt][2] = b1.x; s[nt][3] = b1.y;
        }

        // S += Q K^T (bf16x3)
        #pragma unroll
        for (int ks = 0; ks < 4; ks++) {
            #pragma unroll
            for (int ng = 0; ng < 4; ng++) {
                int n  = (ng << 4) + (((lane >> 4) & 1) << 3) + (lane & 7);
                int kc = (ks << 4) + (((lane >> 3) & 1) << 3);
                uint32_t off = (uint32_t)(n * 144 + kc * 2);
                uint32_t th[4], tl[4];
                ldsm4(th, kvb + off);              // KH
                ldsm4(tl, kvb + 9216 + off);       // KL
                uint32_t bh0[2] = {th[0], th[1]}, bh1[2] = {th[2], th[3]};
                uint32_t bl0[2] = {tl[0], tl[1]}, bl1[2] = {tl[2], tl[3]};
                mma16816(s[ng * 2 + 0], qfh[ks], bh0);
                mma16816(s[ng * 2 + 1], qfh[ks], bh1);
                mma16816(s[ng * 2 + 0], qfh[ks], bl0);
                mma16816(s[ng * 2 + 1], qfh[ks], bl1);
                mma16816(s[ng * 2 + 0], qfl[ks], bh0);
                mma16816(s[ng * 2 + 1], qfl[ks], bh1);
            }
        }

        // mask
        #pragma unroll
        for (int nt = 0; nt < 8; nt++) {
            int col = j0 + (nt << 3) + (tig << 1);
            uchar2 mk = *(const uchar2*)(mrow + col);
            if (mk.x) { s[nt][0] = -1e30f; s[nt][2] = -1e30f; }
            if (mk.y) { s[nt][1] = -1e30f; s[nt][3] = -1e30f; }
        }

        // online softmax (warp-local rows; quad reduction)
        float mx0 = -1e30f, mx1 = -1e30f;
        #pragma unroll
        for (int nt = 0; nt < 8; nt++) {
            mx0 = fmaxf(mx0, fmaxf(s[nt][0], s[nt][1]));
            mx1 = fmaxf(mx1, fmaxf(s[nt][2], s[nt][3]));
        }
        mx0 = fmaxf(mx0, __shfl_xor_sync(0xFFFFFFFFu, mx0, 1));
        mx0 = fmaxf(mx0, __shfl_xor_sync(0xFFFFFFFFu, mx0, 2));
        mx1 = fmaxf(mx1, __shfl_xor_sync(0xFFFFFFFFu, mx1, 1));
        mx1 = fmaxf(mx1, __shfl_xor_sync(0xFFFFFFFFu, mx1, 2));
        float mn0 = fmaxf(m0, mx0), f0 = __expf(m0 - mn0); m0 = mn0;
        float mn1 = fmaxf(m1, mx1), f1 = __expf(m1 - mn1); m1 = mn1;

        float ps0 = 0.0f, ps1 = 0.0f;
        int prow0 = (w * 16 + g) * 144;
        #pragma unroll
        for (int nt = 0; nt < 8; nt++) {
            float p00 = __expf(s[nt][0] - mn0);
            float p01 = __expf(s[nt][1] - mn0);
            float p10 = __expf(s[nt][2] - mn1);
            float p11 = __expf(s[nt][3] - mn1);
            ps0 += p00 + p01;
            ps1 += p10 + p11;
            int cb = ((nt << 3) + (tig << 1)) * 2;
            __nv_bfloat162 h0 = __float22bfloat162_rn(make_float2(p00, p01));
            __nv_bfloat162 l0p = __float22bfloat162_rn(make_float2(
                p00 - __bfloat162float(h0.x), p01 - __bfloat162float(h0.y)));
            __nv_bfloat162 h1 = __float22bfloat162_rn(make_float2(p10, p11));
            __nv_bfloat162 l1p = __float22bfloat162_rn(make_float2(
                p10 - __bfloat162float(h1.x), p11 - __bfloat162float(h1.y)));
            *(__nv_bfloat162*)(smx + AOFF_PH + prow0 + cb)         = h0;
            *(__nv_bfloat162*)(smx + AOFF_PL + prow0 + cb)         = l0p;
            *(__nv_bfloat162*)(smx + AOFF_PH + prow0 + 8*144 + cb) = h1;
            *(__nv_bfloat162*)(smx + AOFF_PL + prow0 + 8*144 + cb) = l1p;
        }
        l0 = l0 * f0 + ps0;
        l1 = l1 * f1 + ps1;
        #pragma unroll
        for (int nt = 0; nt < 8; nt++) {
            o[nt][0] *= f0; o[nt][1] *= f0;
            o[nt][2] *= f1; o[nt][3] *= f1;
        }
        __syncwarp();                    // P rows are warp-private

        // O += P V (bf16x3); V B-frags via ldmatrix.trans from [j][e]
        uint32_t abase = sb + (uint32_t)((w * 16 + (lane & 15)) * 144 + ((lane >> 4) << 4));
        #pragma unroll
        for (int ks = 0; ks < 4; ks++) {
            uint32_t ph[4], pl[4];
            ldsm4(ph, abase + AOFF_PH + ks * 32);
            ldsm4(pl, abase + AOFF_PL + ks * 32);
            #pragma unroll
            for (int eg = 0; eg < 4; eg++) {
                uint32_t voff = (uint32_t)(((ks << 4) + (lane & 15)) * 144 +
                                           (((eg << 4) + ((lane >> 4) << 3)) * 2));
                uint32_t th[4], tl[4];
                ldsm4t(th, kvb + 18432 + voff);    // VH
                ldsm4t(tl, kvb + 27648 + voff);    // VL
                uint32_t bh0[2] = {th[0], th[1]}, bh1[2] = {th[2], th[3]};
                uint32_t bl0[2] = {tl[0], tl[1]}, bl1[2] = {tl[2], tl[3]};
                mma16816(o[eg * 2 + 0], ph, bh0);
                mma16816(o[eg * 2 + 1], ph, bh1);
                mma16816(o[eg * 2 + 0], ph, bl0);
                mma16816(o[eg * 2 + 1], ph, bl1);
                mma16816(o[eg * 2 + 0], pl, bh0);
                mma16816(o[eg * 2 + 1], pl, bh1);
            }
        }
    }

    l0 += __shfl_xor_sync(0xFFFFFFFFu, l0, 1);
    l0 += __shfl_xor_sync(0xFFFFFFFFu, l0, 2);
    l1 += __shfl_xor_sync(0xFFFFFFFFu, l1, 1);
    l1 += __shfl_xor_sync(0xFFFFFFFFu, l1, 2);
    float inv0 = __frcp_rn(l0), inv1 = __frcp_rn(l1);
    #pragma unroll
    for (int nt = 0; nt < 8; nt++) {
        int e = (nt << 3) + (tig << 1);
        #pragma unroll
        for (int half = 0; half < 2; half++) {
            float inv = half ? inv1 : inv0;
            int row = r0 + (half << 3);
            float v0 = o[nt][half * 2]     * inv;
            float v1 = o[nt][half * 2 + 1] * inv;
            __nv_bfloat162 hp = __float22bfloat162_rn(make_float2(v0, v1));
            __nv_bfloat162 lp = __float22bfloat162_rn(make_float2(
                v0 - __bfloat162float(hp.x), v1 - __bfloat162float(hp.y)));
            size_t off = ((size_t)(b << 10) + row) * Dd + h * DHh + e;
            *(__nv_bfloat162*)(g_ath + off) = hp;
            *(__nv_bfloat162*)(g_atl + off) = lp;
        }
    }
}

// ---------------------------------------------------------------------------
// Launch
// ---------------------------------------------------------------------------
extern "C" void kernel_launch(void* const* d_in, const int* in_sizes, int n_in,
                              void* d_out, int out_size) {
    const float*         x      = (const float*)d_in[0];
    const float*         coords = (const float*)d_in[1];
    const unsigned char* mask   = (const unsigned char*)d_in[2];
    const float*         qkv_w  = (const float*)d_in[3];
    const float*         out_w  = (const float*)d_in[4];
    const float*         out_b  = (const float*)d_in[5];
    const float*         w1     = (const float*)d_in[6];
    const float*         b1     = (const float*)d_in[7];
    const float*         w2     = (const float*)d_in[8];
    const float*         b2     = (const float*)d_in[9];
    float*               out    = (float*)d_out;

    static cudaStream_t s2 = nullptr;
    static cudaEvent_t evF = nullptr, evJ = nullptr;
    if (!s2) {
        cudaStreamCreateWithFlags(&s2, cudaStreamNonBlocking);
        cudaEventCreateWithFlags(&evF, cudaEventDisableTiming);
        cudaEventCreateWithFlags(&evJ, cudaEventDisableTiming);
        cudaFuncSetAttribute(k_attn_mma, cudaFuncAttributeMaxDynamicSharedMemorySize, AT_SMEM);
        cudaFuncSetAttribute(k_qkv_mma,  cudaFuncAttributeMaxDynamicSharedMemorySize, GEMM_SMEM);
        cudaFuncSetAttribute(k_out_mma,  cudaFuncAttributeMaxDynamicSharedMemorySize, GEMM_SMEM);
    }

    // fork
    cudaEventRecord(evF, 0);
    cudaStreamWaitEvent(s2, evF, 0);

    // stream s2: bias chain + out_w split (independent of QKV chain)
    k_bias  <<<dim3(32, 32, Bb), 256, 0, s2>>>(coords, w1, b1, w2, b2);
    k_splitT<<<dim3(16, 16), dim3(32, 32), 0, s2>>>(out_w, Dd, Dd, 1);

    // default stream: QKV chain
    k_split_x<<<2048, 256>>>((const float4*)x);
    k_splitT <<<dim3(48, 16), dim3(32, 32)>>>(qkv_w, Dd, 3 * Dd, 0);
    k_qkv_mma<<<dim3(12, 32), 256, GEMM_SMEM>>>();

    // join
    cudaEventRecord(evJ, s2);
    cudaStreamWaitEvent(0, evJ, 0);

    k_attn_mma<<<dim3(16, 32), 128, AT_SMEM>>>(mask);
    k_out_mma <<<dim3(4, 32), 256, GEMM_SMEM>>>(out_b, out);
}

// round 16
// speedup vs baseline: 1.0488x; 1.0488x over previous
#include <cuda_runtime.h>
#include <cuda_bf16.h>
#include <math.h>
#include <stdint.h>

#define Bb   4
#define Nn   1024
#define Dd   512
#define Hh   8
#define DHh  64
#define HIDn 32

// ---------------------------------------------------------------------------
// Static scratch (allocation-free per harness rules)
// ---------------------------------------------------------------------------
__device__ float g_bias[(size_t)Bb*Hh*Nn*Nn];     // [B,H,N,N] additive bias

// bf16 hi/lo operands
__device__ __nv_bfloat16 g_xh[4096*512],  g_xl[4096*512];    // x          [M,K]
__device__ __nv_bfloat16 g_wth[1536*512], g_wtl[1536*512];   // qkv_w^T    [N,K]
__device__ __nv_bfloat16 g_ath[4096*512], g_atl[4096*512];   // att        [M,K]
__device__ __nv_bfloat16 g_owth[512*512], g_owtl[512*512];   // out_w^T    [N,K]
__device__ __nv_bfloat16 g_qh[Bb*Hh*Nn*DHh], g_ql[Bb*Hh*Nn*DHh];  // q (x0.125)
__device__ __nv_bfloat16 g_kh[Bb*Hh*Nn*DHh], g_kl[Bb*Hh*Nn*DHh];
__device__ __nv_bfloat16 g_vh[Bb*Hh*Nn*DHh], g_vl[Bb*Hh*Nn*DHh];

// ---------------------------------------------------------------------------
// Packed fp32x2 FMA (k_bias only — operands pack cleanly there)
// ---------------------------------------------------------------------------
__device__ __forceinline__ float2 ffma2(float2 a, float2 b, float2 c) {
    float2 d;
    asm("fma.rn.f32x2 %0, %1, %2, %3;"
        : "=l"(*(unsigned long long*)&d)
        : "l"(*(unsigned long long*)&a),
          "l"(*(unsigned long long*)&b),
          "l"(*(unsigned long long*)&c));
    return d;
}

// Branch-free exact-GELU (A&S 7.1.26 5-term erf, |err| <= 1.5e-7)
__device__ __forceinline__ float gelu_exact(float x) {
    float z = 0.70710678118654752f * fabsf(x);
    float d = fmaf(0.3275911f, z, 1.0f);
    float t;
    asm("rcp.approx.f32 %0, %1;" : "=f"(t) : "f"(d));
    float p = fmaf(1.061405429f, t, -1.453152027f);
    p = fmaf(p, t, 1.421413741f);
    p = fmaf(p, t, -0.284496736f);
    p = fmaf(p, t, 0.254829592f);
    p *= t;
    float e = __expf(-z * z);
    float erfv = fmaf(-p, e, 1.0f);
    erfv = copysignf(erfv, x);
    float hx = 0.5f * x;
    return fmaf(hx, erfv, hx);
}

// ---------------------------------------------------------------------------
// mma.sync / ldmatrix / cp.async helpers (baseline PTX, OK on plain sm_103)
// ---------------------------------------------------------------------------
__device__ __forceinline__ uint32_t smem_u32(const void* p) {
    uint32_t a;
    asm("{ .reg .u64 t; cvta.to.shared.u64 t, %1; cvt.u32.u64 %0, t; }" : "=r"(a) : "l"(p));
    return a;
}
__device__ __forceinline__ void ldsm4(uint32_t r[4], uint32_t addr) {
    asm volatile("ldmatrix.sync.aligned.m8n8.x4.shared.b16 {%0,%1,%2,%3}, [%4];"
        : "=r"(r[0]), "=r"(r[1]), "=r"(r[2]), "=r"(r[3]) : "r"(addr));
}
__device__ __forceinline__ void ldsm4t(uint32_t r[4], uint32_t addr) {
    asm volatile("ldmatrix.sync.aligned.m8n8.x4.trans.shared.b16 {%0,%1,%2,%3}, [%4];"
        : "=r"(r[0]), "=r"(r[1]), "=r"(r[2]), "=r"(r[3]) : "r"(addr));
}
__device__ __forceinline__ void mma16816(float c[4], const uint32_t a[4], const uint32_t b[2]) {
    asm volatile("mma.sync.aligned.m16n8k16.row.col.f32.bf16.bf16.f32 "
        "{%0,%1,%2,%3}, {%4,%5,%6,%7}, {%8,%9}, {%0,%1,%2,%3};"
        : "+f"(c[0]), "+f"(c[1]), "+f"(c[2]), "+f"(c[3])
        : "r"(a[0]), "r"(a[1]), "r"(a[2]), "r"(a[3]), "r"(b[0]), "r"(b[1]));
}
__device__ __forceinline__ void cp16(uint32_t dst, const void* src) {
    asm volatile("cp.async.ca.shared.global [%0], [%1], 16;" :: "r"(dst), "l"(src));
}
#define CP_COMMIT() asm volatile("cp.async.commit_group;" ::: "memory")
#define CP_WAIT(n)  asm volatile("cp.async.wait_group %0;" :: "n"(n) : "memory")

#define TP 40   // GEMM smem tile pitch (bf16)

// ---------------------------------------------------------------------------
// hi/lo bf16 split kernels (input x + weight transposes)
// ---------------------------------------------------------------------------
__global__ __launch_bounds__(256) void k_split_x(const float4* __restrict__ src) {
    size_t i = (size_t)blockIdx.x * 256 + threadIdx.x;
    float4 v = src[i];
    float a[4] = {v.x, v.y, v.z, v.w};
    __nv_bfloat16 h[4], l[4];
    #pragma unroll
    for (int j = 0; j < 4; j++) {
        h[j] = __float2bfloat16_rn(a[j]);
        l[j] = __float2bfloat16_rn(a[j] - __bfloat162float(h[j]));
    }
    ((__nv_bfloat162*)g_xh)[2*i]   = __halves2bfloat162(h[0], h[1]);
    ((__nv_bfloat162*)g_xh)[2*i+1] = __halves2bfloat162(h[2], h[3]);
    ((__nv_bfloat162*)g_xl)[2*i]   = __halves2bfloat162(l[0], l[1]);
    ((__nv_bfloat162*)g_xl)[2*i+1] = __halves2bfloat162(l[2], l[3]);
}

__global__ void k_splitT(const float* __restrict__ src, int K, int N, int which) {
    __shared__ float ts[32][33];
    int kk = blockIdx.y * 32 + threadIdx.y;
    int nn = blockIdx.x * 32 + threadIdx.x;
    ts[threadIdx.y][threadIdx.x] = src[(size_t)kk * N + nn];
    __syncthreads();
    int on = blockIdx.x * 32 + threadIdx.y;
    int ok = blockIdx.y * 32 + threadIdx.x;
    float v = ts[threadIdx.x][threadIdx.y];
    __nv_bfloat16 h = __float2bfloat16_rn(v);
    __nv_bfloat16 l = __float2bfloat16_rn(v - __bfloat162float(h));
    __nv_bfloat16* hd = which ? g_owth : g_wth;
    __nv_bfloat16* ld = which ? g_owtl : g_wtl;
    hd[(size_t)on * K + ok] = h;
    ld[(size_t)on * K + ok] = l;
}

// ---------------------------------------------------------------------------
// HMMA bf16x3 GEMM mainloop — cp.async double-buffered
// ---------------------------------------------------------------------------
#define TILE_B   (128 * TP * 2)
#define BUF_B    (4 * TILE_B)
#define GEMM_SMEM (2 * BUF_B)

__device__ __forceinline__ void cp_tile(uint32_t dst, const __nv_bfloat16* __restrict__ src,
                                        int row0, int k0, int tid) {
    #pragma unroll
    for (int i = 0; i < 2; i++) {
        int idx = tid + (i << 8);
        int rr = idx >> 2, sg = idx & 3;
        cp16(dst + (uint32_t)((rr * TP) * 2 + sg * 16),
             (const char*)src + ((size_t)(row0 + rr) * 512 + k0) * 2 + sg * 16);
    }
}

__device__ __forceinline__ void issue_chunk(uint32_t sb, int buf,
    const __nv_bfloat16* Ah, const __nv_bfloat16* Al,
    const __nv_bfloat16* Bh, const __nv_bfloat16* Bl,
    int m0, int n0, int k0, int tid)
{
    uint32_t b = sb + buf * BUF_B;
    cp_tile(b + 0 * TILE_B, Ah, m0, k0, tid);
    cp_tile(b + 1 * TILE_B, Al, m0, k0, tid);
    cp_tile(b + 2 * TILE_B, Bh, n0, k0, tid);
    cp_tile(b + 3 * TILE_B, Bl, n0, k0, tid);
    CP_COMMIT();
}

__device__ __forceinline__ void mma_all(float acc[4][4][4],
                                        const uint32_t a[4][4],
                                        const uint32_t b[4][2]) {
    #pragma unroll
    for (int mt = 0; mt < 4; mt++)
        #pragma unroll
        for (int nt = 0; nt < 4; nt++)
            mma16816(acc[mt][nt], a[mt], b[nt]);
}

__device__ __forceinline__ void load_afrag(uint32_t a[4][4], uint32_t base_u32,
                                           int wyBase, int kb, int lane) {
    int r  = wyBase + (lane & 15);
    int kc = (kb << 4) + ((lane >> 4) << 3);
    uint32_t addr = base_u32 + (uint32_t)(r * TP + kc) * 2;
    #pragma unroll
    for (int mt = 0; mt < 4; mt++)
        ldsm4(a[mt], addr + mt * (16 * TP * 2));
}

__device__ __forceinline__ void load_bfrag(uint32_t b[4][2], uint32_t base_u32,
                                           int wxBase, int kb, int lane) {
    int n  = wxBase + (((lane >> 4) & 1) << 3) + (lane & 7);
    int kc = (kb << 4) + (((lane >> 3) & 1) << 3);
    uint32_t addr = base_u32 + (uint32_t)(n * TP + kc) * 2;
    #pragma unroll
    for (int np = 0; np < 2; np++) {
        uint32_t t4[4];
        ldsm4(t4, addr + np * (16 * TP * 2));
        b[np * 2 + 0][0] = t4[0]; b[np * 2 + 0][1] = t4[1];
        b[np * 2 + 1][0] = t4[2]; b[np * 2 + 1][1] = t4[3];
    }
}

__device__ __forceinline__ void hmma_mainloop(
    float acc[4][4][4], char* smem,
    const __nv_bfloat16* Ah, const __nv_bfloat16* Al,
    const __nv_bfloat16* Bh, const __nv_bfloat16* Bl,
    int m0, int n0, int tid)
{
    int lane = tid & 31, wid = tid >> 5;
    int wyBase = (wid >> 2) * 64, wxBase = (wid & 3) * 32;
    uint32_t sb = smem_u32(smem);

    issue_chunk(sb, 0, Ah, Al, Bh, Bl, m0, n0, 0, tid);
    #pragma unroll 1
    for (int c = 0; c < 16; c++) {
        if (c < 15) {
            issue_chunk(sb, (c + 1) & 1, Ah, Al, Bh, Bl, m0, n0, (c + 1) * 32, tid);
            CP_WAIT(1);
        } else {
            CP_WAIT(0);
        }
        __syncthreads();
        uint32_t base = sb + (c & 1) * BUF_B;
        uint32_t uAh = base, uAl = base + TILE_B;
        uint32_t uBh = base + 2 * TILE_B, uBl = base + 3 * TILE_B;
        #pragma unroll
        for (int kb = 0; kb < 2; kb++) {
            uint32_t a[4][4], b[4][2];
            load_afrag(a, uAh, wyBase, kb, lane);
            load_bfrag(b, uBl, wxBase, kb, lane);
            mma_all(acc, a, b);
            load_bfrag(b, uBh, wxBase, kb, lane);
            mma_all(acc, a, b);
            load_afrag(a, uAl, wyBase, kb, lane);
            mma_all(acc, a, b);
        }
        __syncthreads();
    }
}

// ---------------------------------------------------------------------------
// K1: QKV projection on HMMA; epilogue writes q/k/v as bf16 hi/lo (q x0.125).
// ---------------------------------------------------------------------------
__global__ __launch_bounds__(256, 2) void k_qkv_mma() {
    extern __shared__ char smg[];
    int tid = threadIdx.x;
    int n0 = blockIdx.x << 7, m0 = blockIdx.y << 7;

    float acc[4][4][4];
    #pragma unroll
    for (int mt = 0; mt < 4; mt++)
        #pragma unroll
        for (int nt = 0; nt < 4; nt++)
            acc[mt][nt][0] = acc[mt][nt][1] = acc[mt][nt][2] = acc[mt][nt][3] = 0.0f;

    hmma_mainloop(acc, smg, g_xh, g_xl, g_wth, g_wtl, m0, n0, tid);

    int lane = tid & 31, wid = tid >> 5;
    int wyBase = (wid >> 2) * 64, wxBase = (wid & 3) * 32;
    int g = lane >> 2, tig = lane & 3;

    int sec = n0 >> 9;
    float s = (sec == 0) ? 0.125f : 1.0f;
    __nv_bfloat16* dh = (sec == 0) ? g_qh : (sec == 1) ? g_kh : g_vh;
    __nv_bfloat16* dl = (sec == 0) ? g_ql : (sec == 1) ? g_kl : g_vl;

    #pragma unroll
    for (int mt = 0; mt < 4; mt++) {
        #pragma unroll
        for (int nt = 0; nt < 4; nt++) {
            int col = n0 + wxBase + (nt << 3) + (tig << 1);
            int h = (col & 511) >> 6, e = col & 63;
            #pragma unroll
            for (int half = 0; half < 2; half++) {
                int row = m0 + wyBase + (mt << 4) + g + (half << 3);
                int b = row >> 10, n = row & 1023;
                float v0 = acc[mt][nt][half * 2]     * s;
                float v1 = acc[mt][nt][half * 2 + 1] * s;
                __nv_bfloat162 hp = __float22bfloat162_rn(make_float2(v0, v1));
                __nv_bfloat162 lp = __float22bfloat162_rn(make_float2(
                    v0 - __bfloat162float(hp.x), v1 - __bfloat162float(hp.y)));
                size_t off = ((size_t)((b << 3) + h) * Nn + n) * DHh + e;
                *(__nv_bfloat162*)(dh + off) = hp;
                *(__nv_bfloat162*)(dl + off) = lp;
            }
        }
    }
}

// ---------------------------------------------------------------------------
// K4: output projection on HMMA. out = att @ out_w + out_b
// ---------------------------------------------------------------------------
__global__ __launch_bounds__(256, 2) void k_out_mma(const float* __restrict__ bias,
                                                    float* __restrict__ out) {
    extern __shared__ char smg[];
    int tid = threadIdx.x;
    int n0 = blockIdx.x << 7, m0 = blockIdx.y << 7;

    float acc[4][4][4];
    #pragma unroll
    for (int mt = 0; mt < 4; mt++)
        #pragma unroll
        for (int nt = 0; nt < 4; nt++)
            acc[mt][nt][0] = acc[mt][nt][1] = acc[mt][nt][2] = acc[mt][nt][3] = 0.0f;

    hmma_mainloop(acc, smg, g_ath, g_atl, g_owth, g_owtl, m0, n0, tid);

    int lane = tid & 31, wid = tid >> 5;
    int wyBase = (wid >> 2) * 64, wxBase = (wid & 3) * 32;
    int g = lane >> 2, tig = lane & 3;

    #pragma unroll
    for (int mt = 0; mt < 4; mt++) {
        #pragma unroll
        for (int nt = 0; nt < 4; nt++) {
            int col = n0 + wxBase + (nt << 3) + (tig << 1);
            float2 bv = *(const float2*)(bias + col);
            #pragma unroll
            for (int half = 0; half < 2; half++) {
                int row = m0 + wyBase + (mt << 4) + g + (half << 3);
                *(float2*)(out + (size_t)row * Dd + col) =
                    make_float2(acc[mt][nt][half * 2] + bv.x,
                                acc[mt][nt][half * 2 + 1] + bv.y);
            }
        }
    }
}

// ---------------------------------------------------------------------------
// K2: bias MLP (fused proj, fixed coordinate loads)
// ---------------------------------------------------------------------------
__global__ __launch_bounds__(256) void k_bias(const float* __restrict__ coords,
                                              const float* __restrict__ w1,
                                              const float* __restrict__ b1,
                                              const float* __restrict__ w2,
                                              const float* __restrict__ b2) {
    __shared__ float  sUi[32 * 33];
    __shared__ float  sUj[32 * 33];
    __shared__ float  sw1[96];
    __shared__ float  sb1v[32];
    __shared__ float  ci[32][3];
    __shared__ float  cj[32][3];
    __shared__ float2 sw2[HIDn * 4];
    __shared__ float2 sb2v[4];

    int b  = blockIdx.z;
    int i0 = blockIdx.y << 5;
    int j0 = blockIdx.x << 5;
    int tid = threadIdx.x;

    if (tid < 96) {
        sw1[tid] = w1[tid];
        int r = tid / 3, c = tid % 3;
        ci[r][c] = coords[((size_t)(b << 10) + i0 + r) * 3 + c];
        cj[r][c] = coords[((size_t)(b << 10) + j0 + r) * 3 + c];
    }
    if (tid < 32)  sb1v[tid] = b1[tid];
    if (tid >= 128) {
        int t = tid - 128;
        int m = t >> 2, hp = t & 3;
        sw2[m * 4 + hp] = *(const float2*)(w2 + m * Hh + (hp << 1));
    }
    if (tid >= 96 && tid < 100) sb2v[tid - 96] = *(const float2*)(b2 + ((tid - 96) << 1));
    __syncthreads();

    #pragma unroll
    for (int k = 0; k < 4; k++) {
        int idx = tid + (k << 8);
        int r = idx >> 5, m = idx & 31;
        float w0 = sw1[m], w1v = sw1[32 + m], w2v = sw1[64 + m];
        sUi[r * 33 + m] = fmaf(ci[r][0], w0, fmaf(ci[r][1], w1v,
                           fmaf(ci[r][2], w2v, sb1v[m])));
        sUj[r * 33 + m] = fmaf(cj[r][0], w0, fmaf(cj[r][1], w1v, cj[r][2] * w2v));
    }
    __syncthreads();

    int j  = tid & 31;
    int ib = tid >> 5;                       // i = ib + 8q
    const float* uj = sUj + j * 33;
    const float* ui = sUi + ib * 33;

    float2 acc[4][4];
    #pragma unroll
    for (int q = 0; q < 4; q++) {
        acc[q][0] = sb2v[0]; acc[q][1] = sb2v[1];
        acc[q][2] = sb2v[2]; acc[q][3] = sb2v[3];
    }

    #pragma unroll 8
    for (int m = 0; m < HIDn; m++) {
        float ujm = uj[m];
        float2 w0 = sw2[m * 4 + 0], w1v = sw2[m * 4 + 1];
        float2 w2v = sw2[m * 4 + 2], w3v = sw2[m * 4 + 3];
        #pragma unroll
        for (int q = 0; q < 4; q++) {
            float g = gelu_exact(ui[q * 264 + m] - ujm);   // 264 = 8*33
            float2 gg = make_float2(g, g);
            acc[q][0] = ffma2(gg, w0,  acc[q][0]);
            acc[q][1] = ffma2(gg, w1v, acc[q][1]);
            acc[q][2] = ffma2(gg, w2v, acc[q][2]);
            acc[q][3] = ffma2(gg, w3v, acc[q][3]);
        }
    }

    #pragma unroll
    for (int q = 0; q < 4; q++) {
        int i = ib + (q << 3);
        size_t base = ((size_t)((b * Hh) << 10) + i0 + i) * Nn + j0 + j;
        float av[8] = {acc[q][0].x, acc[q][0].y, acc[q][1].x, acc[q][1].y,
                       acc[q][2].x, acc[q][2].y, acc[q][3].x, acc[q][3].y};
        #pragma unroll
        for (int h = 0; h < Hh; h++)
            g_bias[base + (size_t)h * (Nn * Nn)] = av[h];
    }
}

// ---------------------------------------------------------------------------
// K3: HMMA flash attention — R13 geometry: 256 threads / 128 i-rows per CTA,
// cp.async double-buffered K/V. smem: 2x36864 (KV) + 2x18432 (P) = 110592 B.
// ---------------------------------------------------------------------------
#define KVBUF   36864
#define AOFF_PH 73728
#define AOFF_PL 92160
#define AT_SMEM 110592

__device__ __forceinline__ void attn_issue_kv(uint32_t sb, int buf,
    const __nv_bfloat16* Kh, const __nv_bfloat16* Kl,
    const __nv_bfloat16* Vh, const __nv_bfloat16* Vl, int j0, int tid)
{
    // 256 threads: each covers 32B of one row (4 threads/row)
    int row = tid >> 2, off = (tid & 3) * 32;
    size_t go = (size_t)(j0 + row) * DHh;
    uint32_t d = sb + (uint32_t)(buf * KVBUF + row * 144 + off);
    cp16(d + 0,          (const char*)(Kh + go) + off);
    cp16(d + 16,         (const char*)(Kh + go) + off + 16);
    cp16(d + 9216,       (const char*)(Kl + go) + off);
    cp16(d + 9216 + 16,  (const char*)(Kl + go) + off + 16);
    cp16(d + 18432,      (const char*)(Vh + go) + off);
    cp16(d + 18432 + 16, (const char*)(Vh + go) + off + 16);
    cp16(d + 27648,      (const char*)(Vl + go) + off);
    cp16(d + 27648 + 16, (const char*)(Vl + go) + off + 16);
    CP_COMMIT();
}

__global__ __launch_bounds__(256) void k_attn_mma(const unsigned char* __restrict__ mask) {
    extern __shared__ char smx[];
    uint32_t sb = smem_u32(smx);
    int tid = threadIdx.x, lane = tid & 31, w = tid >> 5;
    int g = lane >> 2, tig = lane & 3;
    int bh = blockIdx.y, i0 = blockIdx.x << 7;
    int b = bh >> 3, h = bh & 7;

    const __nv_bfloat16* Qh = g_qh + (size_t)bh * Nn * DHh;
    const __nv_bfloat16* Ql = g_ql + (size_t)bh * Nn * DHh;
    const __nv_bfloat16* Kh = g_kh + (size_t)bh * Nn * DHh;
    const __nv_bfloat16* Kl = g_kl + (size_t)bh * Nn * DHh;
    const __nv_bfloat16* Vh = g_vh + (size_t)bh * Nn * DHh;
    const __nv_bfloat16* Vl = g_vl + (size_t)bh * Nn * DHh;
    const unsigned char* mrow = mask + ((size_t)b << 10);
    int r0 = i0 + w * 16 + g;
    const float* br0 = g_bias + (size_t)bh * Nn * Nn + (size_t)r0 * Nn;
    const float* br1 = br0 + 8 * Nn;

    // prefetch first K/V tile while staging Q
    attn_issue_kv(sb, 0, Kh, Kl, Vh, Vl, 0, tid);

    // stage Q fragments into registers (hi then lo, via P buffer)
    uint32_t qfh[4][4], qfl[4][4];
    #pragma unroll
    for (int pass = 0; pass < 2; pass++) {
        const __nv_bfloat16* src = pass ? Ql : Qh;
        int row = tid >> 1, off = (tid & 1) * 64;
        const uint4* s4 = (const uint4*)((const char*)(src + (size_t)(i0 + row) * DHh) + off);
        uint4* d4 = (uint4*)(smx + AOFF_PH + row * 144 + off);
        d4[0] = s4[0]; d4[1] = s4[1]; d4[2] = s4[2]; d4[3] = s4[3];
        __syncthreads();
        uint32_t base = sb + AOFF_PH + (uint32_t)((w * 16 + (lane & 15)) * 144 + ((lane >> 4) << 4));
        #pragma unroll
        for (int ks = 0; ks < 4; ks++)
            ldsm4(pass ? qfl[ks] : qfh[ks], base + ks * 32);
        __syncthreads();
    }

    float o[8][4];
    #pragma unroll
    for (int nt = 0; nt < 8; nt++)
        o[nt][0] = o[nt][1] = o[nt][2] = o[nt][3] = 0.0f;
    float m0 = -1e30f, m1 = -1e30f, l0 = 0.0f, l1 = 0.0f;

    #pragma unroll 1
    for (int jt = 0; jt < 16; jt++) {
        int j0 = jt << 6;
        CP_WAIT(0);
        __syncthreads();                       // KV ready; prior PV reads done
        if (jt < 15)
            attn_issue_kv(sb, (jt + 1) & 1, Kh, Kl, Vh, Vl, (jt + 1) << 6, tid);

        uint32_t kvb = sb + (uint32_t)((jt & 1) * KVBUF);

        // init S accumulators with bias (MMA accumulates on top)
        float s[8][4];
        #pragma unroll
        for (int nt = 0; nt < 8; nt++) {
            int col = j0 + (nt << 3) + (tig << 1);
            float2 b0 = *(const float2*)(br0 + col);
            float2 b1 = *(const float2*)(br1 + col);
            s[nt][0] = b0.x; s[nt][1] = b0.y;
            s[nt][2] = b1.x; s[nt][3] = b1.y;
        }

        // S += Q K^T (bf16x3)
        #pragma unroll
        for (int ks = 0; ks < 4; ks++) {
            #pragma unroll
            for (int ng = 0; ng < 4; ng++) {
                int n  = (ng << 4) + (((lane >> 4) & 1) << 3) + (lane & 7);
                int kc = (ks << 4) + (((lane >> 3) & 1) << 3);
                uint32_t off = (uint32_t)(n * 144 + kc * 2);
                uint32_t th[4], tl[4];
                ldsm4(th, kvb + off);              // KH
                ldsm4(tl, kvb + 9216 + off);       // KL
                uint32_t bh0[2] = {th[0], th[1]}, bh1[2] = {th[2], th[3]};
                uint32_t bl0[2] = {tl[0], tl[1]}, bl1[2] = {tl[2], tl[3]};
                mma16816(s[ng * 2 + 0], qfh[ks], bh0);
                mma16816(s[ng * 2 + 1], qfh[ks], bh1);
                mma16816(s[ng * 2 + 0], qfh[ks], bl0);
                mma16816(s[ng * 2 + 1], qfh[ks], bl1);
                mma16816(s[ng * 2 + 0], qfl[ks], bh0);
                mma16816(s[ng * 2 + 1], qfl[ks], bh1);
            }
        }

        // mask
        #pragma unroll
        for (int nt = 0; nt < 8; nt++) {
            int col = j0 + (nt << 3) + (tig << 1);
            uchar2 mk = *(const uchar2*)(mrow + col);
            if (mk.x) { s[nt][0] = -1e30f; s[nt][2] = -1e30f; }
            if (mk.y) { s[nt][1] = -1e30f; s[nt][3] = -1e30f; }
        }

        // online softmax (warp-local rows; quad reduction)
        float mx0 = -1e30f, mx1 = -1e30f;
        #pragma unroll
        for (int nt = 0; nt < 8; nt++) {
            mx0 = fmaxf(mx0, fmaxf(s[nt][0], s[nt][1]));
            mx1 = fmaxf(mx1, fmaxf(s[nt][2], s[nt][3]));
        }
        mx0 = fmaxf(mx0, __shfl_xor_sync(0xFFFFFFFFu, mx0, 1));
        mx0 = fmaxf(mx0, __shfl_xor_sync(0xFFFFFFFFu, mx0, 2));
        mx1 = fmaxf(mx1, __shfl_xor_sync(0xFFFFFFFFu, mx1, 1));
        mx1 = fmaxf(mx1, __shfl_xor_sync(0xFFFFFFFFu, mx1, 2));
        float mn0 = fmaxf(m0, mx0), f0 = __expf(m0 - mn0); m0 = mn0;
        float mn1 = fmaxf(m1, mx1), f1 = __expf(m1 - mn1); m1 = mn1;

        float ps0 = 0.0f, ps1 = 0.0f;
        int prow0 = (w * 16 + g) * 144;
        #pragma unroll
        for (int nt = 0; nt < 8; nt++) {
            float p00 = __expf(s[nt][0] - mn0);
            float p01 = __expf(s[nt][1] - mn0);
            float p10 = __expf(s[nt][2] - mn1);
            float p11 = __expf(s[nt][3] - mn1);
            ps0 += p00 + p01;
            ps1 += p10 + p11;
            int cb = ((nt << 3) + (tig << 1)) * 2;
            __nv_bfloat162 h0 = __float22bfloat162_rn(make_float2(p00, p01));
            __nv_bfloat162 l0p = __float22bfloat162_rn(make_float2(
                p00 - __bfloat162float(h0.x), p01 - __bfloat162float(h0.y)));
            __nv_bfloat162 h1 = __float22bfloat162_rn(make_float2(p10, p11));
            __nv_bfloat162 l1p = __float22bfloat162_rn(make_float2(
                p10 - __bfloat162float(h1.x), p11 - __bfloat162float(h1.y)));
            *(__nv_bfloat162*)(smx + AOFF_PH + prow0 + cb)         = h0;
            *(__nv_bfloat162*)(smx + AOFF_PL + prow0 + cb)         = l0p;
            *(__nv_bfloat162*)(smx + AOFF_PH + prow0 + 8*144 + cb) = h1;
            *(__nv_bfloat162*)(smx + AOFF_PL + prow0 + 8*144 + cb) = l1p;
        }
        l0 = l0 * f0 + ps0;
        l1 = l1 * f1 + ps1;
        #pragma unroll
        for (int nt = 0; nt < 8; nt++) {
            o[nt][0] *= f0; o[nt][1] *= f0;
            o[nt][2] *= f1; o[nt][3] *= f1;
        }
        __syncwarp();                    // P rows are warp-private

        // O += P V (bf16x3); V B-frags via ldmatrix.trans from [j][e]
        uint32_t abase = sb + (uint32_t)((w * 16 + (lane & 15)) * 144 + ((lane >> 4) << 4));
        #pragma unroll
        for (int ks = 0; ks < 4; ks++) {
            uint32_t ph[4], pl[4];
            ldsm4(ph, abase + AOFF_PH + ks * 32);
            ldsm4(pl, abase + AOFF_PL + ks * 32);
            #pragma unroll
            for (int eg = 0; eg < 4; eg++) {
                uint32_t voff = (uint32_t)(((ks << 4) + (lane & 15)) * 144 +
                                           (((eg << 4) + ((lane >> 4) << 3)) * 2));
                uint32_t th[4], tl[4];
                ldsm4t(th, kvb + 18432 + voff);    // VH
                ldsm4t(tl, kvb + 27648 + voff);    // VL
                uint32_t bh0[2] = {th[0], th[1]}, bh1[2] = {th[2], th[3]};
                uint32_t bl0[2] = {tl[0], tl[1]}, bl1[2] = {tl[2], tl[3]};
                mma16816(o[eg * 2 + 0], ph, bh0);
                mma16816(o[eg * 2 + 1], ph, bh1);
                mma16816(o[eg * 2 + 0], ph, bl0);
                mma16816(o[eg * 2 + 1], ph, bl1);
                mma16816(o[eg * 2 + 0], pl, bh0);
                mma16816(o[eg * 2 + 1], pl, bh1);
            }
        }
    }

    l0 += __shfl_xor_sync(0xFFFFFFFFu, l0, 1);
    l0 += __shfl_xor_sync(0xFFFFFFFFu, l0, 2);
    l1 += __shfl_xor_sync(0xFFFFFFFFu, l1, 1);
    l1 += __shfl_xor_sync(0xFFFFFFFFu, l1, 2);
    float inv0 = __frcp_rn(l0), inv1 = __frcp_rn(l1);
    #pragma unroll
    for (int nt = 0; nt < 8; nt++) {
        int e = (nt << 3) + (tig << 1);
        #pragma unroll
        for (int half = 0; half < 2; half++) {
            float inv = half ? inv1 : inv0;
            int row = r0 + (half << 3);
            float v0 = o[nt][half * 2]     * inv;
            float v1 = o[nt][half * 2 + 1] * inv;
            __nv_bfloat162 hp = __float22bfloat162_rn(make_float2(v0, v1));
            __nv_bfloat162 lp = __float22bfloat162_rn(make_float2(
                v0 - __bfloat162float(hp.x), v1 - __bfloat162float(hp.y)));
            size_t off = ((size_t)(b << 10) + row) * Dd + h * DHh + e;
            *(__nv_bfloat162*)(g_ath + off) = hp;
            *(__nv_bfloat162*)(g_atl + off) = lp;
        }
    }
}

// ---------------------------------------------------------------------------
// Launch
// ---------------------------------------------------------------------------
extern "C" void kernel_launch(void* const* d_in, const int* in_sizes, int n_in,
                              void* d_out, int out_size) {
    const float*         x      = (const float*)d_in[0];
    const float*         coords = (const float*)d_in[1];
    const unsigned char* mask   = (const unsigned char*)d_in[2];
    const float*         qkv_w  = (const float*)d_in[3];
    const float*         out_w  = (const float*)d_in[4];
    const float*         out_b  = (const float*)d_in[5];
    const float*         w1     = (const float*)d_in[6];
    const float*         b1     = (const float*)d_in[7];
    const float*         w2     = (const float*)d_in[8];
    const float*         b2     = (const float*)d_in[9];
    float*               out    = (float*)d_out;

    static cudaStream_t s2 = nullptr;
    static cudaEvent_t evF = nullptr, evJ = nullptr;
    if (!s2) {
        cudaStreamCreateWithFlags(&s2, cudaStreamNonBlocking);
        cudaEventCreateWithFlags(&evF, cudaEventDisableTiming);
        cudaEventCreateWithFlags(&evJ, cudaEventDisableTiming);
        cudaFuncSetAttribute(k_attn_mma, cudaFuncAttributeMaxDynamicSharedMemorySize, AT_SMEM);
        cudaFuncSetAttribute(k_qkv_mma,  cudaFuncAttributeMaxDynamicSharedMemorySize, GEMM_SMEM);
        cudaFuncSetAttribute(k_out_mma,  cudaFuncAttributeMaxDynamicSharedMemorySize, GEMM_SMEM);
    }

    // fork
    cudaEventRecord(evF, 0);
    cudaStreamWaitEvent(s2, evF, 0);

    // stream s2: bias chain + out_w split (independent of QKV chain)
    k_bias  <<<dim3(32, 32, Bb), 256, 0, s2>>>(coords, w1, b1, w2, b2);
    k_splitT<<<dim3(16, 16), dim3(32, 32), 0, s2>>>(out_w, Dd, Dd, 1);

    // default stream: QKV chain
    k_split_x<<<2048, 256>>>((const float4*)x);
    k_splitT <<<dim3(48, 16), dim3(32, 32)>>>(qkv_w, Dd, 3 * Dd, 0);
    k_qkv_mma<<<dim3(12, 32), 256, GEMM_SMEM>>>();

    // join
    cudaEventRecord(evJ, s2);
    cudaStreamWaitEvent(0, evJ, 0);

    k_attn_mma<<<dim3(8, 32), 256, AT_SMEM>>>(mask);
    k_out_mma <<<dim3(4, 32), 256, GEMM_SMEM>>>(out_b, out);
}

// round 17
// speedup vs baseline: 1.0589x; 1.0097x over previous
#include <cuda_runtime.h>
#include <cuda_bf16.h>
#include <math.h>
#include <stdint.h>

#define Bb   4
#define Nn   1024
#define Dd   512
#define Hh   8
#define DHh  64
#define HIDn 32

// ---------------------------------------------------------------------------
// Static scratch (allocation-free per harness rules)
// ---------------------------------------------------------------------------
__device__ float g_bias[(size_t)Bb*Hh*Nn*Nn];     // [B,H,N,N] additive bias

// bf16 hi/lo operands
__device__ __nv_bfloat16 g_xh[4096*512],  g_xl[4096*512];    // x          [M,K]
__device__ __nv_bfloat16 g_wth[1536*512], g_wtl[1536*512];   // qkv_w^T    [N,K]
__device__ __nv_bfloat16 g_ath[4096*512], g_atl[4096*512];   // att        [M,K]
__device__ __nv_bfloat16 g_owth[512*512], g_owtl[512*512];   // out_w^T    [N,K]
__device__ __nv_bfloat16 g_qh[Bb*Hh*Nn*DHh], g_ql[Bb*Hh*Nn*DHh];  // q (x0.125)
__device__ __nv_bfloat16 g_kh[Bb*Hh*Nn*DHh], g_kl[Bb*Hh*Nn*DHh];
__device__ __nv_bfloat16 g_vh[Bb*Hh*Nn*DHh], g_vl[Bb*Hh*Nn*DHh];

// ---------------------------------------------------------------------------
// Packed fp32x2 FMA (k_bias only — operands pack cleanly there)
// ---------------------------------------------------------------------------
__device__ __forceinline__ float2 ffma2(float2 a, float2 b, float2 c) {
    float2 d;
    asm("fma.rn.f32x2 %0, %1, %2, %3;"
        : "=l"(*(unsigned long long*)&d)
        : "l"(*(unsigned long long*)&a),
          "l"(*(unsigned long long*)&b),
          "l"(*(unsigned long long*)&c));
    return d;
}

// Branch-free exact-GELU (A&S 7.1.26 5-term erf, |err| <= 1.5e-7)
__device__ __forceinline__ float gelu_exact(float x) {
    float z = 0.70710678118654752f * fabsf(x);
    float d = fmaf(0.3275911f, z, 1.0f);
    float t;
    asm("rcp.approx.f32 %0, %1;" : "=f"(t) : "f"(d));
    float p = fmaf(1.061405429f, t, -1.453152027f);
    p = fmaf(p, t, 1.421413741f);
    p = fmaf(p, t, -0.284496736f);
    p = fmaf(p, t, 0.254829592f);
    p *= t;
    float e = __expf(-z * z);
    float erfv = fmaf(-p, e, 1.0f);
    erfv = copysignf(erfv, x);
    float hx = 0.5f * x;
    return fmaf(hx, erfv, hx);
}

// ---------------------------------------------------------------------------
// mma.sync / ldmatrix / cp.async helpers (baseline PTX, OK on plain sm_103)
// ---------------------------------------------------------------------------
__device__ __forceinline__ uint32_t smem_u32(const void* p) {
    uint32_t a;
    asm("{ .reg .u64 t; cvta.to.shared.u64 t, %1; cvt.u32.u64 %0, t; }" : "=r"(a) : "l"(p));
    return a;
}
__device__ __forceinline__ void ldsm4(uint32_t r[4], uint32_t addr) {
    asm volatile("ldmatrix.sync.aligned.m8n8.x4.shared.b16 {%0,%1,%2,%3}, [%4];"
        : "=r"(r[0]), "=r"(r[1]), "=r"(r[2]), "=r"(r[3]) : "r"(addr));
}
__device__ __forceinline__ void ldsm4t(uint32_t r[4], uint32_t addr) {
    asm volatile("ldmatrix.sync.aligned.m8n8.x4.trans.shared.b16 {%0,%1,%2,%3}, [%4];"
        : "=r"(r[0]), "=r"(r[1]), "=r"(r[2]), "=r"(r[3]) : "r"(addr));
}
__device__ __forceinline__ void mma16816(float c[4], const uint32_t a[4], const uint32_t b[2]) {
    asm volatile("mma.sync.aligned.m16n8k16.row.col.f32.bf16.bf16.f32 "
        "{%0,%1,%2,%3}, {%4,%5,%6,%7}, {%8,%9}, {%0,%1,%2,%3};"
        : "+f"(c[0]), "+f"(c[1]), "+f"(c[2]), "+f"(c[3])
        : "r"(a[0]), "r"(a[1]), "r"(a[2]), "r"(a[3]), "r"(b[0]), "r"(b[1]));
}
__device__ __forceinline__ void cp16(uint32_t dst, const void* src) {
    asm volatile("cp.async.ca.shared.global [%0], [%1], 16;" :: "r"(dst), "l"(src));
}
#define CP_COMMIT() asm volatile("cp.async.commit_group;" ::: "memory")
#define CP_WAIT(n)  asm volatile("cp.async.wait_group %0;" :: "n"(n) : "memory")

#define TP 40   // GEMM smem tile pitch (bf16)

// ---------------------------------------------------------------------------
// hi/lo bf16 split kernels (input x + weight transposes)
// ---------------------------------------------------------------------------
__global__ __launch_bounds__(256) void k_split_x(const float4* __restrict__ src) {
    size_t i = (size_t)blockIdx.x * 256 + threadIdx.x;
    float4 v = src[i];
    float a[4] = {v.x, v.y, v.z, v.w};
    __nv_bfloat16 h[4], l[4];
    #pragma unroll
    for (int j = 0; j < 4; j++) {
        h[j] = __float2bfloat16_rn(a[j]);
        l[j] = __float2bfloat16_rn(a[j] - __bfloat162float(h[j]));
    }
    ((__nv_bfloat162*)g_xh)[2*i]   = __halves2bfloat162(h[0], h[1]);
    ((__nv_bfloat162*)g_xh)[2*i+1] = __halves2bfloat162(h[2], h[3]);
    ((__nv_bfloat162*)g_xl)[2*i]   = __halves2bfloat162(l[0], l[1]);
    ((__nv_bfloat162*)g_xl)[2*i+1] = __halves2bfloat162(l[2], l[3]);
}

__global__ void k_splitT(const float* __restrict__ src, int K, int N, int which) {
    __shared__ float ts[32][33];
    int kk = blockIdx.y * 32 + threadIdx.y;
    int nn = blockIdx.x * 32 + threadIdx.x;
    ts[threadIdx.y][threadIdx.x] = src[(size_t)kk * N + nn];
    __syncthreads();
    int on = blockIdx.x * 32 + threadIdx.y;
    int ok = blockIdx.y * 32 + threadIdx.x;
    float v = ts[threadIdx.x][threadIdx.y];
    __nv_bfloat16 h = __float2bfloat16_rn(v);
    __nv_bfloat16 l = __float2bfloat16_rn(v - __bfloat162float(h));
    __nv_bfloat16* hd = which ? g_owth : g_wth;
    __nv_bfloat16* ld = which ? g_owtl : g_wtl;
    hd[(size_t)on * K + ok] = h;
    ld[(size_t)on * K + ok] = l;
}

// ---------------------------------------------------------------------------
// HMMA bf16x3 GEMM mainloop — cp.async double-buffered
// ---------------------------------------------------------------------------
#define TILE_B   (128 * TP * 2)
#define BUF_B    (4 * TILE_B)
#define GEMM_SMEM (2 * BUF_B)

__device__ __forceinline__ void cp_tile(uint32_t dst, const __nv_bfloat16* __restrict__ src,
                                        int row0, int k0, int tid) {
    #pragma unroll
    for (int i = 0; i < 2; i++) {
        int idx = tid + (i << 8);
        int rr = idx >> 2, sg = idx & 3;
        cp16(dst + (uint32_t)((rr * TP) * 2 + sg * 16),
             (const char*)src + ((size_t)(row0 + rr) * 512 + k0) * 2 + sg * 16);
    }
}

__device__ __forceinline__ void issue_chunk(uint32_t sb, int buf,
    const __nv_bfloat16* Ah, const __nv_bfloat16* Al,
    const __nv_bfloat16* Bh, const __nv_bfloat16* Bl,
    int m0, int n0, int k0, int tid)
{
    uint32_t b = sb + buf * BUF_B;
    cp_tile(b + 0 * TILE_B, Ah, m0, k0, tid);
    cp_tile(b + 1 * TILE_B, Al, m0, k0, tid);
    cp_tile(b + 2 * TILE_B, Bh, n0, k0, tid);
    cp_tile(b + 3 * TILE_B, Bl, n0, k0, tid);
    CP_COMMIT();
}

__device__ __forceinline__ void mma_all(float acc[4][4][4],
                                        const uint32_t a[4][4],
                                        const uint32_t b[4][2]) {
    #pragma unroll
    for (int mt = 0; mt < 4; mt++)
        #pragma unroll
        for (int nt = 0; nt < 4; nt++)
            mma16816(acc[mt][nt], a[mt], b[nt]);
}

__device__ __forceinline__ void load_afrag(uint32_t a[4][4], uint32_t base_u32,
                                           int wyBase, int kb, int lane) {
    int r  = wyBase + (lane & 15);
    int kc = (kb << 4) + ((lane >> 4) << 3);
    uint32_t addr = base_u32 + (uint32_t)(r * TP + kc) * 2;
    #pragma unroll
    for (int mt = 0; mt < 4; mt++)
        ldsm4(a[mt], addr + mt * (16 * TP * 2));
}

__device__ __forceinline__ void load_bfrag(uint32_t b[4][2], uint32_t base_u32,
                                           int wxBase, int kb, int lane) {
    int n  = wxBase + (((lane >> 4) & 1) << 3) + (lane & 7);
    int kc = (kb << 4) + (((lane >> 3) & 1) << 3);
    uint32_t addr = base_u32 + (uint32_t)(n * TP + kc) * 2;
    #pragma unroll
    for (int np = 0; np < 2; np++) {
        uint32_t t4[4];
        ldsm4(t4, addr + np * (16 * TP * 2));
        b[np * 2 + 0][0] = t4[0]; b[np * 2 + 0][1] = t4[1];
        b[np * 2 + 1][0] = t4[2]; b[np * 2 + 1][1] = t4[3];
    }
}

__device__ __forceinline__ void hmma_mainloop(
    float acc[4][4][4], char* smem,
    const __nv_bfloat16* Ah, const __nv_bfloat16* Al,
    const __nv_bfloat16* Bh, const __nv_bfloat16* Bl,
    int m0, int n0, int tid)
{
    int lane = tid & 31, wid = tid >> 5;
    int wyBase = (wid >> 2) * 64, wxBase = (wid & 3) * 32;
    uint32_t sb = smem_u32(smem);

    issue_chunk(sb, 0, Ah, Al, Bh, Bl, m0, n0, 0, tid);
    #pragma unroll 1
    for (int c = 0; c < 16; c++) {
        if (c < 15) {
            issue_chunk(sb, (c + 1) & 1, Ah, Al, Bh, Bl, m0, n0, (c + 1) * 32, tid);
            CP_WAIT(1);
        } else {
            CP_WAIT(0);
        }
        __syncthreads();
        uint32_t base = sb + (c & 1) * BUF_B;
        uint32_t uAh = base, uAl = base + TILE_B;
        uint32_t uBh = base + 2 * TILE_B, uBl = base + 3 * TILE_B;
        #pragma unroll
        for (int kb = 0; kb < 2; kb++) {
            uint32_t a[4][4], b[4][2];
            load_afrag(a, uAh, wyBase, kb, lane);
            load_bfrag(b, uBl, wxBase, kb, lane);
            mma_all(acc, a, b);
            load_bfrag(b, uBh, wxBase, kb, lane);
            mma_all(acc, a, b);
            load_afrag(a, uAl, wyBase, kb, lane);
            mma_all(acc, a, b);
        }
        __syncthreads();
    }
}

// ---------------------------------------------------------------------------
// K1: QKV projection on HMMA; epilogue writes q/k/v as bf16 hi/lo (q x0.125).
// ---------------------------------------------------------------------------
__global__ __launch_bounds__(256, 2) void k_qkv_mma() {
    extern __shared__ char smg[];
    int tid = threadIdx.x;
    int n0 = blockIdx.x << 7, m0 = blockIdx.y << 7;

    float acc[4][4][4];
    #pragma unroll
    for (int mt = 0; mt < 4; mt++)
        #pragma unroll
        for (int nt = 0; nt < 4; nt++)
            acc[mt][nt][0] = acc[mt][nt][1] = acc[mt][nt][2] = acc[mt][nt][3] = 0.0f;

    hmma_mainloop(acc, smg, g_xh, g_xl, g_wth, g_wtl, m0, n0, tid);

    int lane = tid & 31, wid = tid >> 5;
    int wyBase = (wid >> 2) * 64, wxBase = (wid & 3) * 32;
    int g = lane >> 2, tig = lane & 3;

    int sec = n0 >> 9;
    float s = (sec == 0) ? 0.125f : 1.0f;
    __nv_bfloat16* dh = (sec == 0) ? g_qh : (sec == 1) ? g_kh : g_vh;
    __nv_bfloat16* dl = (sec == 0) ? g_ql : (sec == 1) ? g_kl : g_vl;

    #pragma unroll
    for (int mt = 0; mt < 4; mt++) {
        #pragma unroll
        for (int nt = 0; nt < 4; nt++) {
            int col = n0 + wxBase + (nt << 3) + (tig << 1);
            int h = (col & 511) >> 6, e = col & 63;
            #pragma unroll
            for (int half = 0; half < 2; half++) {
                int row = m0 + wyBase + (mt << 4) + g + (half << 3);
                int b = row >> 10, n = row & 1023;
                float v0 = acc[mt][nt][half * 2]     * s;
                float v1 = acc[mt][nt][half * 2 + 1] * s;
                __nv_bfloat162 hp = __float22bfloat162_rn(make_float2(v0, v1));
                __nv_bfloat162 lp = __float22bfloat162_rn(make_float2(
                    v0 - __bfloat162float(hp.x), v1 - __bfloat162float(hp.y)));
                size_t off = ((size_t)((b << 3) + h) * Nn + n) * DHh + e;
                *(__nv_bfloat162*)(dh + off) = hp;
                *(__nv_bfloat162*)(dl + off) = lp;
            }
        }
    }
}

// ---------------------------------------------------------------------------
// K4: output projection on HMMA. out = att @ out_w + out_b
// ---------------------------------------------------------------------------
__global__ __launch_bounds__(256, 2) void k_out_mma(const float* __restrict__ bias,
                                                    float* __restrict__ out) {
    extern __shared__ char smg[];
    int tid = threadIdx.x;
    int n0 = blockIdx.x << 7, m0 = blockIdx.y << 7;

    float acc[4][4][4];
    #pragma unroll
    for (int mt = 0; mt < 4; mt++)
        #pragma unroll
        for (int nt = 0; nt < 4; nt++)
            acc[mt][nt][0] = acc[mt][nt][1] = acc[mt][nt][2] = acc[mt][nt][3] = 0.0f;

    hmma_mainloop(acc, smg, g_ath, g_atl, g_owth, g_owtl, m0, n0, tid);

    int lane = tid & 31, wid = tid >> 5;
    int wyBase = (wid >> 2) * 64, wxBase = (wid & 3) * 32;
    int g = lane >> 2, tig = lane & 3;

    #pragma unroll
    for (int mt = 0; mt < 4; mt++) {
        #pragma unroll
        for (int nt = 0; nt < 4; nt++) {
            int col = n0 + wxBase + (nt << 3) + (tig << 1);
            float2 bv = *(const float2*)(bias + col);
            #pragma unroll
            for (int half = 0; half < 2; half++) {
                int row = m0 + wyBase + (mt << 4) + g + (half << 3);
                *(float2*)(out + (size_t)row * Dd + col) =
                    make_float2(acc[mt][nt][half * 2] + bv.x,
                                acc[mt][nt][half * 2 + 1] + bv.y);
            }
        }
    }
}

// ---------------------------------------------------------------------------
// K2: bias MLP (fused proj, fixed coordinate loads)
// ---------------------------------------------------------------------------
__global__ __launch_bounds__(256) void k_bias(const float* __restrict__ coords,
                                              const float* __restrict__ w1,
                                              const float* __restrict__ b1,
                                              const float* __restrict__ w2,
                                              const float* __restrict__ b2) {
    __shared__ float  sUi[32 * 33];
    __shared__ float  sUj[32 * 33];
    __shared__ float  sw1[96];
    __shared__ float  sb1v[32];
    __shared__ float  ci[32][3];
    __shared__ float  cj[32][3];
    __shared__ float2 sw2[HIDn * 4];
    __shared__ float2 sb2v[4];

    int b  = blockIdx.z;
    int i0 = blockIdx.y << 5;
    int j0 = blockIdx.x << 5;
    int tid = threadIdx.x;

    if (tid < 96) {
        sw1[tid] = w1[tid];
        int r = tid / 3, c = tid % 3;
        ci[r][c] = coords[((size_t)(b << 10) + i0 + r) * 3 + c];
        cj[r][c] = coords[((size_t)(b << 10) + j0 + r) * 3 + c];
    }
    if (tid < 32)  sb1v[tid] = b1[tid];
    if (tid >= 128) {
        int t = tid - 128;
        int m = t >> 2, hp = t & 3;
        sw2[m * 4 + hp] = *(const float2*)(w2 + m * Hh + (hp << 1));
    }
    if (tid >= 96 && tid < 100) sb2v[tid - 96] = *(const float2*)(b2 + ((tid - 96) << 1));
    __syncthreads();

    #pragma unroll
    for (int k = 0; k < 4; k++) {
        int idx = tid + (k << 8);
        int r = idx >> 5, m = idx & 31;
        float w0 = sw1[m], w1v = sw1[32 + m], w2v = sw1[64 + m];
        sUi[r * 33 + m] = fmaf(ci[r][0], w0, fmaf(ci[r][1], w1v,
                           fmaf(ci[r][2], w2v, sb1v[m])));
        sUj[r * 33 + m] = fmaf(cj[r][0], w0, fmaf(cj[r][1], w1v, cj[r][2] * w2v));
    }
    __syncthreads();

    int j  = tid & 31;
    int ib = tid >> 5;                       // i = ib + 8q
    const float* uj = sUj + j * 33;
    const float* ui = sUi + ib * 33;

    float2 acc[4][4];
    #pragma unroll
    for (int q = 0; q < 4; q++) {
        acc[q][0] = sb2v[0]; acc[q][1] = sb2v[1];
        acc[q][2] = sb2v[2]; acc[q][3] = sb2v[3];
    }

    #pragma unroll 8
    for (int m = 0; m < HIDn; m++) {
        float ujm = uj[m];
        float2 w0 = sw2[m * 4 + 0], w1v = sw2[m * 4 + 1];
        float2 w2v = sw2[m * 4 + 2], w3v = sw2[m * 4 + 3];
        #pragma unroll
        for (int q = 0; q < 4; q++) {
            float g = gelu_exact(ui[q * 264 + m] - ujm);   // 264 = 8*33
            float2 gg = make_float2(g, g);
            acc[q][0] = ffma2(gg, w0,  acc[q][0]);
            acc[q][1] = ffma2(gg, w1v, acc[q][1]);
            acc[q][2] = ffma2(gg, w2v, acc[q][2]);
            acc[q][3] = ffma2(gg, w3v, acc[q][3]);
        }
    }

    #pragma unroll
    for (int q = 0; q < 4; q++) {
        int i = ib + (q << 3);
        size_t base = ((size_t)((b * Hh) << 10) + i0 + i) * Nn + j0 + j;
        float av[8] = {acc[q][0].x, acc[q][0].y, acc[q][1].x, acc[q][1].y,
                       acc[q][2].x, acc[q][2].y, acc[q][3].x, acc[q][3].y};
        #pragma unroll
        for (int h = 0; h < Hh; h++)
            g_bias[base + (size_t)h * (Nn * Nn)] = av[h];
    }
}

// ---------------------------------------------------------------------------
// K3: HMMA flash attention — 256 threads / 128 i-rows per CTA, forced
// 2 CTAs/SM via launch bounds (2 x 108KB smem = 216KB <= 228KB; 128 regs).
// cp.async double-buffered K/V. smem: 2x36864 (KV) + 2x18432 (P) = 110592 B.
// ---------------------------------------------------------------------------
#define KVBUF   36864
#define AOFF_PH 73728
#define AOFF_PL 92160
#define AT_SMEM 110592

__device__ __forceinline__ void attn_issue_kv(uint32_t sb, int buf,
    const __nv_bfloat16* Kh, const __nv_bfloat16* Kl,
    const __nv_bfloat16* Vh, const __nv_bfloat16* Vl, int j0, int tid)
{
    // 256 threads: each covers 32B of one row (4 threads/row)
    int row = tid >> 2, off = (tid & 3) * 32;
    size_t go = (size_t)(j0 + row) * DHh;
    uint32_t d = sb + (uint32_t)(buf * KVBUF + row * 144 + off);
    cp16(d + 0,          (const char*)(Kh + go) + off);
    cp16(d + 16,         (const char*)(Kh + go) + off + 16);
    cp16(d + 9216,       (const char*)(Kl + go) + off);
    cp16(d + 9216 + 16,  (const char*)(Kl + go) + off + 16);
    cp16(d + 18432,      (const char*)(Vh + go) + off);
    cp16(d + 18432 + 16, (const char*)(Vh + go) + off + 16);
    cp16(d + 27648,      (const char*)(Vl + go) + off);
    cp16(d + 27648 + 16, (const char*)(Vl + go) + off + 16);
    CP_COMMIT();
}

__global__ __launch_bounds__(256, 2) void k_attn_mma(const unsigned char* __restrict__ mask) {
    extern __shared__ char smx[];
    uint32_t sb = smem_u32(smx);
    int tid = threadIdx.x, lane = tid & 31, w = tid >> 5;
    int g = lane >> 2, tig = lane & 3;
    int bh = blockIdx.y, i0 = blockIdx.x << 7;
    int b = bh >> 3, h = bh & 7;

    const __nv_bfloat16* Qh = g_qh + (size_t)bh * Nn * DHh;
    const __nv_bfloat16* Ql = g_ql + (size_t)bh * Nn * DHh;
    const __nv_bfloat16* Kh = g_kh + (size_t)bh * Nn * DHh;
    const __nv_bfloat16* Kl = g_kl + (size_t)bh * Nn * DHh;
    const __nv_bfloat16* Vh = g_vh + (size_t)bh * Nn * DHh;
    const __nv_bfloat16* Vl = g_vl + (size_t)bh * Nn * DHh;
    const unsigned char* mrow = mask + ((size_t)b << 10);
    int r0 = i0 + w * 16 + g;
    const float* br0 = g_bias + (size_t)bh * Nn * Nn + (size_t)r0 * Nn;
    const float* br1 = br0 + 8 * Nn;

    // prefetch first K/V tile while staging Q
    attn_issue_kv(sb, 0, Kh, Kl, Vh, Vl, 0, tid);

    // stage Q fragments into registers (hi then lo, via P buffer)
    uint32_t qfh[4][4], qfl[4][4];
    #pragma unroll
    for (int pass = 0; pass < 2; pass++) {
        const __nv_bfloat16* src = pass ? Ql : Qh;
        int row = tid >> 1, off = (tid & 1) * 64;
        const uint4* s4 = (const uint4*)((const char*)(src + (size_t)(i0 + row) * DHh) + off);
        uint4* d4 = (uint4*)(smx + AOFF_PH + row * 144 + off);
        d4[0] = s4[0]; d4[1] = s4[1]; d4[2] = s4[2]; d4[3] = s4[3];
        __syncthreads();
        uint32_t base = sb + AOFF_PH + (uint32_t)((w * 16 + (lane & 15)) * 144 + ((lane >> 4) << 4));
        #pragma unroll
        for (int ks = 0; ks < 4; ks++)
            ldsm4(pass ? qfl[ks] : qfh[ks], base + ks * 32);
        __syncthreads();
    }

    float o[8][4];
    #pragma unroll
    for (int nt = 0; nt < 8; nt++)
        o[nt][0] = o[nt][1] = o[nt][2] = o[nt][3] = 0.0f;
    float m0 = -1e30f, m1 = -1e30f, l0 = 0.0f, l1 = 0.0f;

    #pragma unroll 1
    for (int jt = 0; jt < 16; jt++) {
        int j0 = jt << 6;
        CP_WAIT(0);
        __syncthreads();                       // KV ready; prior PV reads done
        if (jt < 15)
            attn_issue_kv(sb, (jt + 1) & 1, Kh, Kl, Vh, Vl, (jt + 1) << 6, tid);

        uint32_t kvb = sb + (uint32_t)((jt & 1) * KVBUF);

        // init S accumulators with bias (MMA accumulates on top)
        float s[8][4];
        #pragma unroll
        for (int nt = 0; nt < 8; nt++) {
            int col = j0 + (nt << 3) + (tig << 1);
            float2 b0 = *(const float2*)(br0 + col);
            float2 b1 = *(const float2*)(br1 + col);
            s[nt][0] = b0.x; s[nt][1] = b0.y;
            s[nt][2] = b1.x; s[nt][3] = b1.y;
        }

        // S += Q K^T (bf16x3)
        #pragma unroll
        for (int ks = 0; ks < 4; ks++) {
            #pragma unroll
            for (int ng = 0; ng < 4; ng++) {
                int n  = (ng << 4) + (((lane >> 4) & 1) << 3) + (lane & 7);
                int kc = (ks << 4) + (((lane >> 3) & 1) << 3);
                uint32_t off = (uint32_t)(n * 144 + kc * 2);
                uint32_t th[4], tl[4];
                ldsm4(th, kvb + off);              // KH
                ldsm4(tl, kvb + 9216 + off);       // KL
                uint32_t bh0[2] = {th[0], th[1]}, bh1[2] = {th[2], th[3]};
                uint32_t bl0[2] = {tl[0], tl[1]}, bl1[2] = {tl[2], tl[3]};
                mma16816(s[ng * 2 + 0], qfh[ks], bh0);
                mma16816(s[ng * 2 + 1], qfh[ks], bh1);
                mma16816(s[ng * 2 + 0], qfh[ks], bl0);
                mma16816(s[ng * 2 + 1], qfh[ks], bl1);
                mma16816(s[ng * 2 + 0], qfl[ks], bh0);
                mma16816(s[ng * 2 + 1], qfl[ks], bh1);
            }
        }

        // mask
        #pragma unroll
        for (int nt = 0; nt < 8; nt++) {
            int col = j0 + (nt << 3) + (tig << 1);
            uchar2 mk = *(const uchar2*)(mrow + col);
            if (mk.x) { s[nt][0] = -1e30f; s[nt][2] = -1e30f; }
            if (mk.y) { s[nt][1] = -1e30f; s[nt][3] = -1e30f; }
        }

        // online softmax (warp-local rows; quad reduction)
        float mx0 = -1e30f, mx1 = -1e30f;
        #pragma unroll
        for (int nt = 0; nt < 8; nt++) {
            mx0 = fmaxf(mx0, fmaxf(s[nt][0], s[nt][1]));
            mx1 = fmaxf(mx1, fmaxf(s[nt][2], s[nt][3]));
        }
        mx0 = fmaxf(mx0, __shfl_xor_sync(0xFFFFFFFFu, mx0, 1));
        mx0 = fmaxf(mx0, __shfl_xor_sync(0xFFFFFFFFu, mx0, 2));
        mx1 = fmaxf(mx1, __shfl_xor_sync(0xFFFFFFFFu, mx1, 1));
        mx1 = fmaxf(mx1, __shfl_xor_sync(0xFFFFFFFFu, mx1, 2));
        float mn0 = fmaxf(m0, mx0), f0 = __expf(m0 - mn0); m0 = mn0;
        float mn1 = fmaxf(m1, mx1), f1 = __expf(m1 - mn1); m1 = mn1;

        float ps0 = 0.0f, ps1 = 0.0f;
        int prow0 = (w * 16 + g) * 144;
        #pragma unroll
        for (int nt = 0; nt < 8; nt++) {
            float p00 = __expf(s[nt][0] - mn0);
            float p01 = __expf(s[nt][1] - mn0);
            float p10 = __expf(s[nt][2] - mn1);
            float p11 = __expf(s[nt][3] - mn1);
            ps0 += p00 + p01;
            ps1 += p10 + p11;
            int cb = ((nt << 3) + (tig << 1)) * 2;
            __nv_bfloat162 h0 = __float22bfloat162_rn(make_float2(p00, p01));
            __nv_bfloat162 l0p = __float22bfloat162_rn(make_float2(
                p00 - __bfloat162float(h0.x), p01 - __bfloat162float(h0.y)));
            __nv_bfloat162 h1 = __float22bfloat162_rn(make_float2(p10, p11));
            __nv_bfloat162 l1p = __float22bfloat162_rn(make_float2(
                p10 - __bfloat162float(h1.x), p11 - __bfloat162float(h1.y)));
            *(__nv_bfloat162*)(smx + AOFF_PH + prow0 + cb)         = h0;
            *(__nv_bfloat162*)(smx + AOFF_PL + prow0 + cb)         = l0p;
            *(__nv_bfloat162*)(smx + AOFF_PH + prow0 + 8*144 + cb) = h1;
            *(__nv_bfloat162*)(smx + AOFF_PL + prow0 + 8*144 + cb) = l1p;
        }
        l0 = l0 * f0 + ps0;
        l1 = l1 * f1 + ps1;
        #pragma unroll
        for (int nt = 0; nt < 8; nt++) {
            o[nt][0] *= f0; o[nt][1] *= f0;
            o[nt][2] *= f1; o[nt][3] *= f1;
        }
        __syncwarp();                    // P rows are warp-private

        // O += P V (bf16x3); V B-frags via ldmatrix.trans from [j][e]
        uint32_t abase = sb + (uint32_t)((w * 16 + (lane & 15)) * 144 + ((lane >> 4) << 4));
        #pragma unroll
        for (int ks = 0; ks < 4; ks++) {
            uint32_t ph[4], pl[4];
            ldsm4(ph, abase + AOFF_PH + ks * 32);
            ldsm4(pl, abase + AOFF_PL + ks * 32);
            #pragma unroll
            for (int eg = 0; eg < 4; eg++) {
                uint32_t voff = (uint32_t)(((ks << 4) + (lane & 15)) * 144 +
                                           (((eg << 4) + ((lane >> 4) << 3)) * 2));
                uint32_t th[4], tl[4];
                ldsm4t(th, kvb + 18432 + voff);    // VH
                ldsm4t(tl, kvb + 27648 + voff);    // VL
                uint32_t bh0[2] = {th[0], th[1]}, bh1[2] = {th[2], th[3]};
                uint32_t bl0[2] = {tl[0], tl[1]}, bl1[2] = {tl[2], tl[3]};
                mma16816(o[eg * 2 + 0], ph, bh0);
                mma16816(o[eg * 2 + 1], ph, bh1);
                mma16816(o[eg * 2 + 0], ph, bl0);
                mma16816(o[eg * 2 + 1], ph, bl1);
                mma16816(o[eg * 2 + 0], pl, bh0);
                mma16816(o[eg * 2 + 1], pl, bh1);
            }
        }
    }

    l0 += __shfl_xor_sync(0xFFFFFFFFu, l0, 1);
    l0 += __shfl_xor_sync(0xFFFFFFFFu, l0, 2);
    l1 += __shfl_xor_sync(0xFFFFFFFFu, l1, 1);
    l1 += __shfl_xor_sync(0xFFFFFFFFu, l1, 2);
    float inv0 = __frcp_rn(l0), inv1 = __frcp_rn(l1);
    #pragma unroll
    for (int nt = 0; nt < 8; nt++) {
        int e = (nt << 3) + (tig << 1);
        #pragma unroll
        for (int half = 0; half < 2; half++) {
            float inv = half ? inv1 : inv0;
            int row = r0 + (half << 3);
            float v0 = o[nt][half * 2]     * inv;
            float v1 = o[nt][half * 2 + 1] * inv;
            __nv_bfloat162 hp = __float22bfloat162_rn(make_float2(v0, v1));
            __nv_bfloat162 lp = __float22bfloat162_rn(make_float2(
                v0 - __bfloat162float(hp.x), v1 - __bfloat162float(hp.y)));
            size_t off = ((size_t)(b << 10) + row) * Dd + h * DHh + e;
            *(__nv_bfloat162*)(g_ath + off) = hp;
            *(__nv_bfloat162*)(g_atl + off) = lp;
        }
    }
}

// ---------------------------------------------------------------------------
// Launch
// ---------------------------------------------------------------------------
extern "C" void kernel_launch(void* const* d_in, const int* in_sizes, int n_in,
                              void* d_out, int out_size) {
    const float*         x      = (const float*)d_in[0];
    const float*         coords = (const float*)d_in[1];
    const unsigned char* mask   = (const unsigned char*)d_in[2];
    const float*         qkv_w  = (const float*)d_in[3];
    const float*         out_w  = (const float*)d_in[4];
    const float*         out_b  = (const float*)d_in[5];
    const float*         w1     = (const float*)d_in[6];
    const float*         b1     = (const float*)d_in[7];
    const float*         w2     = (const float*)d_in[8];
    const float*         b2     = (const float*)d_in[9];
    float*               out    = (float*)d_out;

    static cudaStream_t s2 = nullptr;
    static cudaEvent_t evF = nullptr, evJ = nullptr;
    if (!s2) {
        cudaStreamCreateWithFlags(&s2, cudaStreamNonBlocking);
        cudaEventCreateWithFlags(&evF, cudaEventDisableTiming);
        cudaEventCreateWithFlags(&evJ, cudaEventDisableTiming);
        cudaFuncSetAttribute(k_attn_mma, cudaFuncAttributeMaxDynamicSharedMemorySize, AT_SMEM);
        cudaFuncSetAttribute(k_qkv_mma,  cudaFuncAttributeMaxDynamicSharedMemorySize, GEMM_SMEM);
        cudaFuncSetAttribute(k_out_mma,  cudaFuncAttributeMaxDynamicSharedMemorySize, GEMM_SMEM);
    }

    // fork
    cudaEventRecord(evF, 0);
    cudaStreamWaitEvent(s2, evF, 0);

    // stream s2: bias chain + out_w split (independent of QKV chain)
    k_bias  <<<dim3(32, 32, Bb), 256, 0, s2>>>(coords, w1, b1, w2, b2);
    k_splitT<<<dim3(16, 16), dim3(32, 32), 0, s2>>>(out_w, Dd, Dd, 1);

    // default stream: QKV chain
    k_split_x<<<2048, 256>>>((const float4*)x);
    k_splitT <<<dim3(48, 16), dim3(32, 32)>>>(qkv_w, Dd, 3 * Dd, 0);
    k_qkv_mma<<<dim3(12, 32), 256, GEMM_SMEM>>>();

    // join
    cudaEventRecord(evJ, s2);
    cudaStreamWaitEvent(0, evJ, 0);

    k_attn_mma<<<dim3(8, 32), 256, AT_SMEM>>>(mask);
    k_out_mma <<<dim3(4, 32), 256, GEMM_SMEM>>>(out_b, out);
}